// round 1
// baseline (speedup 1.0000x reference)
#include <cuda_runtime.h>
#include <math.h>

#define NN 100000
#define NE 3200000
#define NL 1000000
#define F_IN 512
#define H1 128
#define H2 64

// ---------------- scratch (static device globals; no allocs) ----------------
__device__ float g_h1lin[(size_t)NN * H1];
__device__ float g_h1   [(size_t)NN * H1];
__device__ float g_h2lin[(size_t)NN * H2];
__device__ float g_h2   [(size_t)NN * H2];
__device__ float g_dinv [NN];
__device__ int   g_count[NN];
__device__ int   g_rowptr[NN + 1];
__device__ int   g_cursor[NN];
__device__ int   g_csr  [NE];

// ---------------- CSR build ----------------
__global__ void k_zero_count() {
    int i = blockIdx.x * blockDim.x + threadIdx.x;
    if (i < NN) g_count[i] = 0;
}

__global__ void k_hist(const int* __restrict__ dst) {
    int i = blockIdx.x * blockDim.x + threadIdx.x;
    if (i < NE) atomicAdd(&g_count[dst[i]], 1);
}

__global__ void k_dinv() {
    int i = blockIdx.x * blockDim.x + threadIdx.x;
    if (i < NN) g_dinv[i] = rsqrtf((float)(g_count[i] + 1));  // +1 self loop
}

// single-block scan of g_count -> g_rowptr (exclusive), also seeds g_cursor
__global__ void k_scan() {
    __shared__ int wsum[32];
    __shared__ int carry;
    int tid = threadIdx.x, lane = tid & 31, wid = tid >> 5;
    if (tid == 0) carry = 0;
    __syncthreads();
    for (int base = 0; base < NN; base += 1024) {
        int i = base + tid;
        int v = (i < NN) ? g_count[i] : 0;
        int x = v;
        #pragma unroll
        for (int o = 1; o < 32; o <<= 1) {
            int y = __shfl_up_sync(0xffffffffu, x, o);
            if (lane >= o) x += y;
        }
        if (lane == 31) wsum[wid] = x;
        __syncthreads();
        if (wid == 0) {
            int w = wsum[lane];
            #pragma unroll
            for (int o = 1; o < 32; o <<= 1) {
                int y = __shfl_up_sync(0xffffffffu, w, o);
                if (lane >= o) w += y;
            }
            wsum[lane] = w;
        }
        __syncthreads();
        int excl = carry + (wid ? wsum[wid - 1] : 0) + x - v;
        if (i < NN) { g_rowptr[i] = excl; g_cursor[i] = excl; }
        __syncthreads();
        if (tid == 0) carry += wsum[31];
        __syncthreads();
    }
    if (tid == 0) g_rowptr[NN] = carry;
}

__global__ void k_fill(const int* __restrict__ src, const int* __restrict__ dst) {
    int i = blockIdx.x * blockDim.x + threadIdx.x;
    if (i < NE) {
        int p = atomicAdd(&g_cursor[dst[i]], 1);
        g_csr[p] = src[i];
    }
}

// ---------------- tiled SGEMM: C[M,N] = A[M,K] @ B[K,N] (row-major) ----------------
template <int BM, int BN, int BK, int TM, int TN>
__global__ void sgemm(const float* __restrict__ A, const float* __restrict__ B,
                      float* __restrict__ C, int M, int N, int K) {
    constexpr int THREADS = (BM / TM) * (BN / TN);
    constexpr int ALOADS = (BM * BK) / (4 * THREADS);
    constexpr int BLOADS = (BK * BN) / (4 * THREADS);
    __shared__ float As[BK][BM];
    __shared__ float Bs[BK][BN];
    const int tid = threadIdx.x;
    const int tx = tid % (BN / TN);
    const int ty = tid / (BN / TN);
    const int rowBase = blockIdx.x * BM;

    float acc[TM][TN];
    #pragma unroll
    for (int i = 0; i < TM; i++)
        #pragma unroll
        for (int j = 0; j < TN; j++) acc[i][j] = 0.f;

    for (int kt = 0; kt < K; kt += BK) {
        #pragma unroll
        for (int l = 0; l < ALOADS; l++) {
            int lin = tid + l * THREADS;            // float4 index
            int row = lin / (BK / 4);
            int kc4 = (lin % (BK / 4)) * 4;
            int grow = rowBase + row;
            float4 v = make_float4(0.f, 0.f, 0.f, 0.f);
            if (grow < M)
                v = *(const float4*)&A[(size_t)grow * K + kt + kc4];
            As[kc4 + 0][row] = v.x;
            As[kc4 + 1][row] = v.y;
            As[kc4 + 2][row] = v.z;
            As[kc4 + 3][row] = v.w;
        }
        #pragma unroll
        for (int l = 0; l < BLOADS; l++) {
            int lin = tid + l * THREADS;
            int kr = lin / (BN / 4);
            int nc = (lin % (BN / 4)) * 4;
            *(float4*)&Bs[kr][nc] = *(const float4*)&B[(size_t)(kt + kr) * N + nc];
        }
        __syncthreads();
        #pragma unroll
        for (int k = 0; k < BK; k++) {
            float rm[TM], rn[TN];
            #pragma unroll
            for (int i = 0; i < TM; i++) rm[i] = As[k][ty * TM + i];
            #pragma unroll
            for (int j = 0; j < TN; j++) rn[j] = Bs[k][tx * TN + j];
            #pragma unroll
            for (int i = 0; i < TM; i++)
                #pragma unroll
                for (int j = 0; j < TN; j++) acc[i][j] += rm[i] * rn[j];
        }
        __syncthreads();
    }
    #pragma unroll
    for (int i = 0; i < TM; i++) {
        int r = rowBase + ty * TM + i;
        if (r < M) {
            #pragma unroll
            for (int j = 0; j < TN; j += 4) {
                *(float4*)&C[(size_t)r * N + tx * TN + j] =
                    make_float4(acc[i][j], acc[i][j + 1], acc[i][j + 2], acc[i][j + 3]);
            }
        }
    }
}

// ---------------- gather aggregation: out = relu(D^-1/2 (A+I) D^-1/2 hlin + b) ----------------
__global__ void k_agg128(const float* __restrict__ bias) {
    int gw = (blockIdx.x * blockDim.x + threadIdx.x) >> 5;
    int lane = threadIdx.x & 31;
    if (gw >= NN) return;
    float dd = g_dinv[gw];
    const float4* H = (const float4*)g_h1lin;
    float4 acc = H[(size_t)gw * 32 + lane];
    float w0 = dd * dd;
    acc.x *= w0; acc.y *= w0; acc.z *= w0; acc.w *= w0;
    int s0 = g_rowptr[gw], s1 = g_rowptr[gw + 1];
    for (int base = s0; base < s1; base += 32) {
        int rem = s1 - base;
        int s = 0; float nm = 0.f;
        if (lane < rem) { s = g_csr[base + lane]; nm = dd * g_dinv[s]; }
        int cnt = rem < 32 ? rem : 32;
        for (int j = 0; j < cnt; j++) {
            int ss = __shfl_sync(0xffffffffu, s, j);
            float nn = __shfl_sync(0xffffffffu, nm, j);
            float4 hv = H[(size_t)ss * 32 + lane];
            acc.x += nn * hv.x; acc.y += nn * hv.y;
            acc.z += nn * hv.z; acc.w += nn * hv.w;
        }
    }
    float4 bb = ((const float4*)bias)[lane];
    float4 r;
    r.x = fmaxf(acc.x + bb.x, 0.f);
    r.y = fmaxf(acc.y + bb.y, 0.f);
    r.z = fmaxf(acc.z + bb.z, 0.f);
    r.w = fmaxf(acc.w + bb.w, 0.f);
    ((float4*)g_h1)[(size_t)gw * 32 + lane] = r;
}

__global__ void k_agg64(const float* __restrict__ bias) {
    int gw = (blockIdx.x * blockDim.x + threadIdx.x) >> 5;
    int lane = threadIdx.x & 31;
    if (gw >= NN) return;
    float dd = g_dinv[gw];
    const float2* H = (const float2*)g_h2lin;
    float2 acc = H[(size_t)gw * 32 + lane];
    float w0 = dd * dd;
    acc.x *= w0; acc.y *= w0;
    int s0 = g_rowptr[gw], s1 = g_rowptr[gw + 1];
    for (int base = s0; base < s1; base += 32) {
        int rem = s1 - base;
        int s = 0; float nm = 0.f;
        if (lane < rem) { s = g_csr[base + lane]; nm = dd * g_dinv[s]; }
        int cnt = rem < 32 ? rem : 32;
        for (int j = 0; j < cnt; j++) {
            int ss = __shfl_sync(0xffffffffu, s, j);
            float nn = __shfl_sync(0xffffffffu, nm, j);
            float2 hv = H[(size_t)ss * 32 + lane];
            acc.x += nn * hv.x; acc.y += nn * hv.y;
        }
    }
    float2 bb = ((const float2*)bias)[lane];
    float2 r;
    r.x = fmaxf(acc.x + bb.x, 0.f);
    r.y = fmaxf(acc.y + bb.y, 0.f);
    ((float2*)g_h2)[(size_t)gw * 32 + lane] = r;
}

// ---------------- edge scorer: out = relu((h2[a]*h2[b]) @ fcW1 + fcb1) @ fcW2 + fcb2 ----------------
__global__ void k_score(const int* __restrict__ la, const int* __restrict__ lb,
                        const float* __restrict__ fcW1, const float* __restrict__ fcb1,
                        const float* __restrict__ fcW2, const float* __restrict__ fcb2,
                        float* __restrict__ out) {
    __shared__ float W1s[64 * 64];
    __shared__ float Tst[64][65];
    const int tid = threadIdx.x;
    const int e0 = blockIdx.x * 64;

    #pragma unroll
    for (int l = 0; l < 4; l++) {
        int f = tid + l * 256;  // float4 index, 0..1023
        *(float4*)&W1s[f * 4] = *(const float4*)&fcW1[f * 4];
    }
    #pragma unroll
    for (int l = 0; l < 16; l++) {
        int idx = tid + l * 256;   // 0..4095
        int e = idx >> 6;
        int k = idx & 63;
        int a = la[e0 + e], b = lb[e0 + e];
        Tst[k][e] = g_h2[(size_t)a * 64 + k] * g_h2[(size_t)b * 64 + k];
    }
    __syncthreads();

    const int tx = tid & 15, ty = tid >> 4;
    float acc[4][4];
    #pragma unroll
    for (int i = 0; i < 4; i++)
        #pragma unroll
        for (int j = 0; j < 4; j++) acc[i][j] = 0.f;

    #pragma unroll
    for (int k = 0; k < 64; k++) {
        float4 rn = *(float4*)&W1s[k * 64 + tx * 4];
        float rm[4];
        #pragma unroll
        for (int i = 0; i < 4; i++) rm[i] = Tst[k][ty * 4 + i];
        #pragma unroll
        for (int i = 0; i < 4; i++) {
            acc[i][0] += rm[i] * rn.x;
            acc[i][1] += rm[i] * rn.y;
            acc[i][2] += rm[i] * rn.z;
            acc[i][3] += rm[i] * rn.w;
        }
    }

    float4 bb = *(const float4*)&fcb1[tx * 4];
    float w20[4], w21[4];
    #pragma unroll
    for (int j = 0; j < 4; j++) {
        w20[j] = fcW2[(tx * 4 + j) * 2 + 0];
        w21[j] = fcW2[(tx * 4 + j) * 2 + 1];
    }
    float c0 = fcb2[0], c1 = fcb2[1];
    #pragma unroll
    for (int i = 0; i < 4; i++) {
        float u0 = fmaxf(acc[i][0] + bb.x, 0.f);
        float u1 = fmaxf(acc[i][1] + bb.y, 0.f);
        float u2 = fmaxf(acc[i][2] + bb.z, 0.f);
        float u3 = fmaxf(acc[i][3] + bb.w, 0.f);
        float p0 = u0 * w20[0] + u1 * w20[1] + u2 * w20[2] + u3 * w20[3];
        float p1 = u0 * w21[0] + u1 * w21[1] + u2 * w21[2] + u3 * w21[3];
        #pragma unroll
        for (int off = 8; off; off >>= 1) {
            p0 += __shfl_down_sync(0xffffffffu, p0, off, 16);
            p1 += __shfl_down_sync(0xffffffffu, p1, off, 16);
        }
        if (tx == 0) {
            int e = e0 + ty * 4 + i;
            out[(size_t)e * 2 + 0] = p0 + c0;
            out[(size_t)e * 2 + 1] = p1 + c1;
        }
    }
}

// ---------------- launch ----------------
extern "C" void kernel_launch(void* const* d_in, const int* in_sizes, int n_in,
                              void* d_out, int out_size) {
    const float* x    = (const float*)d_in[0];
    const float* W1   = (const float*)d_in[1];
    const float* b1   = (const float*)d_in[2];
    const float* W2   = (const float*)d_in[3];
    const float* b2   = (const float*)d_in[4];
    const float* fcW1 = (const float*)d_in[5];
    const float* fcb1 = (const float*)d_in[6];
    const float* fcW2 = (const float*)d_in[7];
    const float* fcb2 = (const float*)d_in[8];
    const int* eidx = (const int*)d_in[9];
    const int* elab = (const int*)d_in[10];
    const int* src = eidx;
    const int* dst = eidx + NE;
    const int* la = elab;
    const int* lb = elab + NL;
    float* out = (float*)d_out;

    float *p_h1lin, *p_h1, *p_h2lin, *p_h2;
    cudaGetSymbolAddress((void**)&p_h1lin, g_h1lin);
    cudaGetSymbolAddress((void**)&p_h1,    g_h1);
    cudaGetSymbolAddress((void**)&p_h2lin, g_h2lin);
    cudaGetSymbolAddress((void**)&p_h2,    g_h2);

    // CSR build + degrees
    k_zero_count<<<(NN + 255) / 256, 256>>>();
    k_hist<<<(NE + 255) / 256, 256>>>(dst);
    k_dinv<<<(NN + 255) / 256, 256>>>();
    k_scan<<<1, 1024>>>();
    k_fill<<<(NE + 255) / 256, 256>>>(src, dst);

    // layer 1
    sgemm<128, 128, 16, 8, 8><<<dim3((NN + 127) / 128, 1), 256>>>(x, W1, p_h1lin, NN, H1, F_IN);
    k_agg128<<<(NN * 32 + 255) / 256, 256>>>(b1);

    // layer 2
    sgemm<128, 64, 16, 8, 4><<<dim3((NN + 127) / 128, 1), 256>>>(p_h1, W2, p_h2lin, NN, H2, H1);
    k_agg64<<<(NN * 32 + 255) / 256, 256>>>(b2);

    // scorer
    k_score<<<NL / 64, 256>>>(la, lb, fcW1, fcb1, fcW2, fcb2, out);
}

// round 3
// speedup vs baseline: 1.1920x; 1.1920x over previous
#include <cuda_runtime.h>
#include <math.h>
#include <stdint.h>

#define NN 100000
#define NE 3200000
#define NL 1000000
#define F_IN 512
#define H1 128
#define H2 64
#define NBLK ((NN + 1023) / 1024)

// ---------------- scratch (static device globals; no allocs) ----------------
__device__ float g_h1lin[(size_t)NN * H1];
__device__ float g_h1   [(size_t)NN * H1];
__device__ float g_h2lin[(size_t)NN * H2];
__device__ float g_h2   [(size_t)NN * H2];
__device__ float g_dinv [NN];
__device__ int   g_count[NN];
__device__ int   g_rowptr[NN + 1];
__device__ int   g_cursor[NN];
__device__ int   g_csr  [NE];
__device__ int   g_bsum [NBLK];
__device__ int   g_bpre [NBLK];
__device__ float g_whT[(size_t)H1 * F_IN];   // W1^T hi  [128][512]
__device__ float g_wlT[(size_t)H1 * F_IN];   // W1^T lo

// ---------------- helpers ----------------
__device__ __forceinline__ uint32_t smem_u32(const void* p) {
    uint32_t a;
    asm("{ .reg .u64 t; cvta.to.shared.u64 t, %1; cvt.u32.u64 %0, t; }" : "=r"(a) : "l"(p));
    return a;
}
__device__ __forceinline__ float tf32r(float x) {
    uint32_t u;
    asm("cvt.rna.tf32.f32 %0, %1;" : "=r"(u) : "f"(x));
    return __uint_as_float(u);
}
// m16n8k8 tf32 mma: D += A*B, acc float[4], a uint[4], b uint[2]
#define MMA(c, a, b) \
    asm volatile("mma.sync.aligned.m16n8k8.row.col.f32.tf32.tf32.f32 " \
                 "{%0,%1,%2,%3}, {%4,%5,%6,%7}, {%8,%9}, {%0,%1,%2,%3};" \
                 : "+f"((c)[0]), "+f"((c)[1]), "+f"((c)[2]), "+f"((c)[3]) \
                 : "r"((a)[0]), "r"((a)[1]), "r"((a)[2]), "r"((a)[3]), \
                   "r"((b)[0]), "r"((b)[1]))

// ---------------- CSR build ----------------
__global__ void k_zero_count() {
    int i = blockIdx.x * blockDim.x + threadIdx.x;
    if (i < NN) g_count[i] = 0;
}
__global__ void k_hist(const int* __restrict__ dst) {
    int i = blockIdx.x * blockDim.x + threadIdx.x;
    if (i < NE) atomicAdd(&g_count[dst[i]], 1);
}
__global__ void k_dinv() {
    int i = blockIdx.x * blockDim.x + threadIdx.x;
    if (i < NN) g_dinv[i] = rsqrtf((float)(g_count[i] + 1));
}
__global__ void k_bsum() {
    __shared__ int ws[32];
    int t = threadIdx.x, lane = t & 31, wid = t >> 5;
    int i = blockIdx.x * 1024 + t;
    int v = (i < NN) ? g_count[i] : 0;
    #pragma unroll
    for (int o = 16; o; o >>= 1) v += __shfl_down_sync(0xffffffffu, v, o);
    if (lane == 0) ws[wid] = v;
    __syncthreads();
    if (wid == 0) {
        int x = ws[lane];
        #pragma unroll
        for (int o = 16; o; o >>= 1) x += __shfl_down_sync(0xffffffffu, x, o);
        if (lane == 0) g_bsum[blockIdx.x] = x;
    }
}
__global__ void k_bscan() {
    __shared__ int ws[4];
    int t = threadIdx.x, lane = t & 31, wid = t >> 5;
    int v = (t < NBLK) ? g_bsum[t] : 0;
    int x = v;
    #pragma unroll
    for (int o = 1; o < 32; o <<= 1) {
        int y = __shfl_up_sync(0xffffffffu, x, o);
        if (lane >= o) x += y;
    }
    if (lane == 31) ws[wid] = x;
    __syncthreads();
    int add = 0;
    for (int w = 0; w < wid; w++) add += ws[w];
    int incl = x + add;
    if (t < NBLK) g_bpre[t] = incl - v;
    if (t == 127) g_rowptr[NN] = incl;
}
__global__ void k_scat() {
    __shared__ int ws[32];
    int t = threadIdx.x, lane = t & 31, wid = t >> 5;
    int i = blockIdx.x * 1024 + t;
    int v = (i < NN) ? g_count[i] : 0;
    int x = v;
    #pragma unroll
    for (int o = 1; o < 32; o <<= 1) {
        int y = __shfl_up_sync(0xffffffffu, x, o);
        if (lane >= o) x += y;
    }
    if (lane == 31) ws[wid] = x;
    __syncthreads();
    if (wid == 0) {
        int w = ws[lane];
        #pragma unroll
        for (int o = 1; o < 32; o <<= 1) {
            int y = __shfl_up_sync(0xffffffffu, w, o);
            if (lane >= o) w += y;
        }
        ws[lane] = w;
    }
    __syncthreads();
    int excl = g_bpre[blockIdx.x] + (wid ? ws[wid - 1] : 0) + x - v;
    if (i < NN) { g_rowptr[i] = excl; g_cursor[i] = excl; }
}
__global__ void k_fill(const int* __restrict__ src, const int* __restrict__ dst) {
    int i = blockIdx.x * blockDim.x + threadIdx.x;
    if (i < NE) {
        int p = atomicAdd(&g_cursor[dst[i]], 1);
        g_csr[p] = src[i];
    }
}

// ---------------- W1 transpose + tf32 hi/lo split ----------------
__global__ void k_wsplit(const float* __restrict__ W1) {
    int i = blockIdx.x * blockDim.x + threadIdx.x;
    if (i < H1 * F_IN) {
        int n = i & (H1 - 1);
        int k = i >> 7;
        float w = W1[(size_t)k * H1 + n];
        float h = tf32r(w);
        float l = tf32r(w - h);
        g_whT[(size_t)n * F_IN + k] = h;
        g_wlT[(size_t)n * F_IN + k] = l;
    }
}

// ---------------- GEMM1 via mma.sync tf32x3: C[100000,128] = A @ W1 ----------------
// block tile 128x128, BK=32, double-buffered. smem stage (floats):
//   Ah @0, Al @4608, Bh @9216, Bl @13824 (each 128 rows x 32 k, stride 36)
#define G1_STAGE_F 18432
#define G1_SMEM (2 * G1_STAGE_F * 4)

__global__ void __launch_bounds__(256, 1)
k_gemm1_mma(const float* __restrict__ A, float* __restrict__ C) {
    extern __shared__ float sm[];
    const int tid = threadIdx.x, lane = tid & 31, wid = tid >> 5;
    const int rowBase = blockIdx.x * 128;
    const int wm = (wid >> 1) * 32, wn = (wid & 1) * 64;

    float acc[2][8][4];
    #pragma unroll
    for (int mt = 0; mt < 2; mt++)
        #pragma unroll
        for (int nt = 0; nt < 8; nt++)
            #pragma unroll
            for (int i = 0; i < 4; i++) acc[mt][nt][i] = 0.f;

    float4 pa[4];
    auto ldgA = [&](int kt) {
        #pragma unroll
        for (int l = 0; l < 4; l++) {
            int f = tid + l * 256;
            int row = f >> 3, c4 = f & 7;
            int gr = rowBase + row;
            pa[l] = (gr < NN) ? *(const float4*)&A[(size_t)gr * F_IN + kt + c4 * 4]
                              : make_float4(0.f, 0.f, 0.f, 0.f);
        }
    };
    auto stsA = [&](float* buf) {
        #pragma unroll
        for (int l = 0; l < 4; l++) {
            int f = tid + l * 256;
            int row = f >> 3, c4 = f & 7;
            float4 v = pa[l];
            float hx = tf32r(v.x), hy = tf32r(v.y), hz = tf32r(v.z), hw = tf32r(v.w);
            float lx = tf32r(v.x - hx), ly = tf32r(v.y - hy);
            float lz = tf32r(v.z - hz), lw = tf32r(v.w - hw);
            *(float4*)&buf[row * 36 + c4 * 4]        = make_float4(hx, hy, hz, hw);
            *(float4*)&buf[4608 + row * 36 + c4 * 4] = make_float4(lx, ly, lz, lw);
        }
    };
    auto cpB = [&](int kt, float* buf) {
        #pragma unroll
        for (int l = 0; l < 8; l++) {
            int idx = tid + l * 256;
            int sel = idx >> 10;           // 0: hi, 1: lo
            int j = idx & 1023;
            int r = j >> 3, c4 = j & 7;
            const float* g = (sel ? g_wlT : g_whT) + (size_t)r * F_IN + kt + c4 * 4;
            float* s = buf + 9216 + sel * 4608 + r * 36 + c4 * 4;
            uint32_t sa = smem_u32(s);
            asm volatile("cp.async.cg.shared.global [%0], [%1], 16;\n" :: "r"(sa), "l"(g));
        }
        asm volatile("cp.async.commit_group;\n");
    };

    ldgA(0);
    cpB(0, sm);
    stsA(sm);
    asm volatile("cp.async.wait_group 0;\n");
    __syncthreads();

    for (int s = 0; s < 16; s++) {
        float* cur = sm + (s & 1) * G1_STAGE_F;
        float* nxt = sm + ((s + 1) & 1) * G1_STAGE_F;
        if (s + 1 < 16) { cpB((s + 1) * 32, nxt); ldgA((s + 1) * 32); }

        const float* Ah = cur;
        const float* Al = cur + 4608;
        const float* Bh = cur + 9216;
        const float* Bl = cur + 13824;
        const int rA = wm + (lane >> 2);
        const int cA = lane & 3;
        const int cB = lane >> 2;
        const int rB = lane & 3;

        #pragma unroll
        for (int ks = 0; ks < 4; ks++) {
            int kb = ks * 8;
            uint32_t ah[2][4], al[2][4];
            #pragma unroll
            for (int mt = 0; mt < 2; mt++) {
                int rr = rA + mt * 16;
                ah[mt][0] = __float_as_uint(Ah[rr * 36 + kb + cA]);
                ah[mt][1] = __float_as_uint(Ah[(rr + 8) * 36 + kb + cA]);
                ah[mt][2] = __float_as_uint(Ah[rr * 36 + kb + cA + 4]);
                ah[mt][3] = __float_as_uint(Ah[(rr + 8) * 36 + kb + cA + 4]);
                al[mt][0] = __float_as_uint(Al[rr * 36 + kb + cA]);
                al[mt][1] = __float_as_uint(Al[(rr + 8) * 36 + kb + cA]);
                al[mt][2] = __float_as_uint(Al[rr * 36 + kb + cA + 4]);
                al[mt][3] = __float_as_uint(Al[(rr + 8) * 36 + kb + cA + 4]);
            }
            uint32_t bh[8][2], bl[8][2];
            #pragma unroll
            for (int nt = 0; nt < 8; nt++) {
                int cc = wn + nt * 8 + cB;
                bh[nt][0] = __float_as_uint(Bh[cc * 36 + kb + rB]);
                bh[nt][1] = __float_as_uint(Bh[cc * 36 + kb + rB + 4]);
                bl[nt][0] = __float_as_uint(Bl[cc * 36 + kb + rB]);
                bl[nt][1] = __float_as_uint(Bl[cc * 36 + kb + rB + 4]);
            }
            #pragma unroll
            for (int mt = 0; mt < 2; mt++)
                #pragma unroll
                for (int nt = 0; nt < 8; nt++) {
                    MMA(acc[mt][nt], ah[mt], bh[nt]);
                    MMA(acc[mt][nt], al[mt], bh[nt]);
                    MMA(acc[mt][nt], ah[mt], bl[nt]);
                }
        }
        if (s + 1 < 16) { stsA(nxt); asm volatile("cp.async.wait_group 0;\n"); }
        __syncthreads();
    }

    #pragma unroll
    for (int mt = 0; mt < 2; mt++) {
        int row = rowBase + wm + mt * 16 + (lane >> 2);
        #pragma unroll
        for (int nt = 0; nt < 8; nt++) {
            int col = wn + nt * 8 + (lane & 3) * 2;
            if (row < NN)
                *(float2*)&C[(size_t)row * H1 + col] =
                    make_float2(acc[mt][nt][0], acc[mt][nt][1]);
            if (row + 8 < NN)
                *(float2*)&C[(size_t)(row + 8) * H1 + col] =
                    make_float2(acc[mt][nt][2], acc[mt][nt][3]);
        }
    }
}

// ---------------- fp32 tiled SGEMM (layer 2) ----------------
template <int BM, int BN, int BK, int TM, int TN>
__global__ void sgemm(const float* __restrict__ A, const float* __restrict__ B,
                      float* __restrict__ C, int M, int N, int K) {
    constexpr int THREADS = (BM / TM) * (BN / TN);
    constexpr int ALOADS = (BM * BK) / (4 * THREADS);
    constexpr int BLOADS = (BK * BN) / (4 * THREADS);
    __shared__ float As[BK][BM];
    __shared__ float Bs[BK][BN];
    const int tid = threadIdx.x;
    const int tx = tid % (BN / TN);
    const int ty = tid / (BN / TN);
    const int rowBase = blockIdx.x * BM;

    float acc[TM][TN];
    #pragma unroll
    for (int i = 0; i < TM; i++)
        #pragma unroll
        for (int j = 0; j < TN; j++) acc[i][j] = 0.f;

    for (int kt = 0; kt < K; kt += BK) {
        #pragma unroll
        for (int l = 0; l < ALOADS; l++) {
            int lin = tid + l * THREADS;
            int row = lin / (BK / 4);
            int kc4 = (lin % (BK / 4)) * 4;
            int grow = rowBase + row;
            float4 v = make_float4(0.f, 0.f, 0.f, 0.f);
            if (grow < M)
                v = *(const float4*)&A[(size_t)grow * K + kt + kc4];
            As[kc4 + 0][row] = v.x;
            As[kc4 + 1][row] = v.y;
            As[kc4 + 2][row] = v.z;
            As[kc4 + 3][row] = v.w;
        }
        #pragma unroll
        for (int l = 0; l < BLOADS; l++) {
            int lin = tid + l * THREADS;
            int kr = lin / (BN / 4);
            int nc = (lin % (BN / 4)) * 4;
            *(float4*)&Bs[kr][nc] = *(const float4*)&B[(size_t)(kt + kr) * N + nc];
        }
        __syncthreads();
        #pragma unroll
        for (int k = 0; k < BK; k++) {
            float rm[TM], rn[TN];
            #pragma unroll
            for (int i = 0; i < TM; i++) rm[i] = As[k][ty * TM + i];
            #pragma unroll
            for (int j = 0; j < TN; j++) rn[j] = Bs[k][tx * TN + j];
            #pragma unroll
            for (int i = 0; i < TM; i++)
                #pragma unroll
                for (int j = 0; j < TN; j++) acc[i][j] += rm[i] * rn[j];
        }
        __syncthreads();
    }
    #pragma unroll
    for (int i = 0; i < TM; i++) {
        int r = rowBase + ty * TM + i;
        if (r < M) {
            #pragma unroll
            for (int j = 0; j < TN; j += 4) {
                *(float4*)&C[(size_t)r * N + tx * TN + j] =
                    make_float4(acc[i][j], acc[i][j + 1], acc[i][j + 2], acc[i][j + 3]);
            }
        }
    }
}

// ---------------- gather aggregation ----------------
__global__ void k_agg128(const float* __restrict__ bias) {
    int gw = (blockIdx.x * blockDim.x + threadIdx.x) >> 5;
    int lane = threadIdx.x & 31;
    if (gw >= NN) return;
    float dd = g_dinv[gw];
    const float4* H = (const float4*)g_h1lin;
    float4 acc = H[(size_t)gw * 32 + lane];
    float w0 = dd * dd;
    acc.x *= w0; acc.y *= w0; acc.z *= w0; acc.w *= w0;
    int s0 = g_rowptr[gw], s1 = g_rowptr[gw + 1];
    for (int base = s0; base < s1; base += 32) {
        int rem = s1 - base;
        int s = 0; float nm = 0.f;
        if (lane < rem) { s = g_csr[base + lane]; nm = dd * g_dinv[s]; }
        int cnt = rem < 32 ? rem : 32;
        for (int j = 0; j < cnt; j++) {
            int ss = __shfl_sync(0xffffffffu, s, j);
            float nn = __shfl_sync(0xffffffffu, nm, j);
            float4 hv = H[(size_t)ss * 32 + lane];
            acc.x += nn * hv.x; acc.y += nn * hv.y;
            acc.z += nn * hv.z; acc.w += nn * hv.w;
        }
    }
    float4 bb = ((const float4*)bias)[lane];
    float4 r;
    r.x = fmaxf(acc.x + bb.x, 0.f);
    r.y = fmaxf(acc.y + bb.y, 0.f);
    r.z = fmaxf(acc.z + bb.z, 0.f);
    r.w = fmaxf(acc.w + bb.w, 0.f);
    ((float4*)g_h1)[(size_t)gw * 32 + lane] = r;
}

__global__ void k_agg64(const float* __restrict__ bias) {
    int gw = (blockIdx.x * blockDim.x + threadIdx.x) >> 5;
    int lane = threadIdx.x & 31;
    if (gw >= NN) return;
    float dd = g_dinv[gw];
    const float2* H = (const float2*)g_h2lin;
    float2 acc = H[(size_t)gw * 32 + lane];
    float w0 = dd * dd;
    acc.x *= w0; acc.y *= w0;
    int s0 = g_rowptr[gw], s1 = g_rowptr[gw + 1];
    for (int base = s0; base < s1; base += 32) {
        int rem = s1 - base;
        int s = 0; float nm = 0.f;
        if (lane < rem) { s = g_csr[base + lane]; nm = dd * g_dinv[s]; }
        int cnt = rem < 32 ? rem : 32;
        for (int j = 0; j < cnt; j++) {
            int ss = __shfl_sync(0xffffffffu, s, j);
            float nn = __shfl_sync(0xffffffffu, nm, j);
            float2 hv = H[(size_t)ss * 32 + lane];
            acc.x += nn * hv.x; acc.y += nn * hv.y;
        }
    }
    float2 bb = ((const float2*)bias)[lane];
    float2 r;
    r.x = fmaxf(acc.x + bb.x, 0.f);
    r.y = fmaxf(acc.y + bb.y, 0.f);
    ((float2*)g_h2)[(size_t)gw * 32 + lane] = r;
}

// ---------------- edge scorer via mma.sync tf32x3 ----------------
// block: 128 edges. smem (floats): Th@0(9216) Tl@9216 Wh@18432(4608) Wl@23040
//   U@27648 (128x65=8320) w2s@35968(128) b1s@36096(64) -> 36160 floats
#define SC_SMEM (36160 * 4)

__global__ void __launch_bounds__(256, 1)
k_score_mma(const int* __restrict__ la, const int* __restrict__ lb,
            const float* __restrict__ fcW1, const float* __restrict__ fcb1,
            const float* __restrict__ fcW2, const float* __restrict__ fcb2,
            float* __restrict__ out) {
    extern __shared__ float sm[];
    float* Th = sm;
    float* Tl = sm + 9216;
    float* Wh = sm + 18432;
    float* Wl = sm + 23040;
    float* U  = sm + 27648;
    float* w2s = sm + 35968;
    float* b1s = sm + 36096;
    const int tid = threadIdx.x, lane = tid & 31, wid = tid >> 5;
    const int e0 = blockIdx.x * 128;

    #pragma unroll
    for (int l = 0; l < 16; l++) {
        int idx = tid + l * 256;               // 4096 = 64x64
        float w = fcW1[idx];
        float h = tf32r(w);
        Wh[(idx >> 6) * 72 + (idx & 63)] = h;
        Wl[(idx >> 6) * 72 + (idx & 63)] = tf32r(w - h);
    }
    if (tid < 128) w2s[tid] = fcW2[tid];
    if (tid < 64)  b1s[tid] = fcb1[tid];

    #pragma unroll
    for (int l = 0; l < 8; l++) {
        int idx = tid + l * 256;               // 2048 = 128 edges x 16 float4
        int e = idx >> 4, c4 = idx & 15;
        int eg = e0 + e;
        if (eg >= NL) eg = NL - 1;
        int a = la[eg], b = lb[eg];
        float4 va = *(const float4*)&g_h2[(size_t)a * H2 + c4 * 4];
        float4 vb = *(const float4*)&g_h2[(size_t)b * H2 + c4 * 4];
        float px = va.x * vb.x, py = va.y * vb.y, pz = va.z * vb.z, pw = va.w * vb.w;
        float hx = tf32r(px), hy = tf32r(py), hz = tf32r(pz), hw = tf32r(pw);
        *(float4*)&Th[e * 72 + c4 * 4] = make_float4(hx, hy, hz, hw);
        *(float4*)&Tl[e * 72 + c4 * 4] =
            make_float4(tf32r(px - hx), tf32r(py - hy), tf32r(pz - hz), tf32r(pw - hw));
    }
    __syncthreads();

    float acc[8][4];
    #pragma unroll
    for (int nt = 0; nt < 8; nt++)
        #pragma unroll
        for (int i = 0; i < 4; i++) acc[nt][i] = 0.f;

    const int rA = wid * 16 + (lane >> 2), cA = lane & 3;
    const int cB = lane >> 2, rB = lane & 3;
    #pragma unroll
    for (int ks = 0; ks < 8; ks++) {
        int kb = ks * 8;
        uint32_t ah[4], al[4];
        ah[0] = __float_as_uint(Th[rA * 72 + kb + cA]);
        ah[1] = __float_as_uint(Th[(rA + 8) * 72 + kb + cA]);
        ah[2] = __float_as_uint(Th[rA * 72 + kb + cA + 4]);
        ah[3] = __float_as_uint(Th[(rA + 8) * 72 + kb + cA + 4]);
        al[0] = __float_as_uint(Tl[rA * 72 + kb + cA]);
        al[1] = __float_as_uint(Tl[(rA + 8) * 72 + kb + cA]);
        al[2] = __float_as_uint(Tl[rA * 72 + kb + cA + 4]);
        al[3] = __float_as_uint(Tl[(rA + 8) * 72 + kb + cA + 4]);
        #pragma unroll
        for (int nt = 0; nt < 8; nt++) {
            int cc = nt * 8 + cB;
            uint32_t bh[2], bl[2];
            bh[0] = __float_as_uint(Wh[(kb + rB) * 72 + cc]);
            bh[1] = __float_as_uint(Wh[(kb + rB + 4) * 72 + cc]);
            bl[0] = __float_as_uint(Wl[(kb + rB) * 72 + cc]);
            bl[1] = __float_as_uint(Wl[(kb + rB + 4) * 72 + cc]);
            MMA(acc[nt], ah, bh);
            MMA(acc[nt], al, bh);
            MMA(acc[nt], ah, bl);
        }
    }

    int row0 = wid * 16 + (lane >> 2);
    #pragma unroll
    for (int nt = 0; nt < 8; nt++) {
        int col = nt * 8 + (lane & 3) * 2;
        float b0v = b1s[col], b1v = b1s[col + 1];
        U[row0 * 65 + col]       = fmaxf(acc[nt][0] + b0v, 0.f);
        U[row0 * 65 + col + 1]   = fmaxf(acc[nt][1] + b1v, 0.f);
        U[(row0 + 8) * 65 + col]     = fmaxf(acc[nt][2] + b0v, 0.f);
        U[(row0 + 8) * 65 + col + 1] = fmaxf(acc[nt][3] + b1v, 0.f);
    }
    __syncthreads();

    int e = tid & 127, j = tid >> 7;
    int eg = e0 + e;
    if (eg < NL) {
        float s = 0.f;
        #pragma unroll
        for (int k = 0; k < 64; k++) s += U[e * 65 + k] * w2s[k * 2 + j];
        out[(size_t)eg * 2 + j] = s + fcb2[j];
    }
}

// ---------------- launch ----------------
extern "C" void kernel_launch(void* const* d_in, const int* in_sizes, int n_in,
                              void* d_out, int out_size) {
    const float* x    = (const float*)d_in[0];
    const float* W1   = (const float*)d_in[1];
    const float* b1   = (const float*)d_in[2];
    const float* W2   = (const float*)d_in[3];
    const float* b2   = (const float*)d_in[4];
    const float* fcW1 = (const float*)d_in[5];
    const float* fcb1 = (const float*)d_in[6];
    const float* fcW2 = (const float*)d_in[7];
    const float* fcb2 = (const float*)d_in[8];
    const int* eidx = (const int*)d_in[9];
    const int* elab = (const int*)d_in[10];
    const int* src = eidx;
    const int* dst = eidx + NE;
    const int* la = elab;
    const int* lb = elab + NL;
    float* out = (float*)d_out;

    float *p_h1lin, *p_h1, *p_h2lin;
    cudaGetSymbolAddress((void**)&p_h1lin, g_h1lin);
    cudaGetSymbolAddress((void**)&p_h1,    g_h1);
    cudaGetSymbolAddress((void**)&p_h2lin, g_h2lin);

    static int attr_done = 0;
    if (!attr_done) {
        cudaFuncSetAttribute(k_gemm1_mma, cudaFuncAttributeMaxDynamicSharedMemorySize, G1_SMEM);
        cudaFuncSetAttribute(k_score_mma, cudaFuncAttributeMaxDynamicSharedMemorySize, SC_SMEM);
        attr_done = 1;
    }

    // CSR build + degrees
    k_zero_count<<<(NN + 255) / 256, 256>>>();
    k_hist<<<(NE + 255) / 256, 256>>>(dst);
    k_dinv<<<(NN + 255) / 256, 256>>>();
    k_bsum<<<NBLK, 1024>>>();
    k_bscan<<<1, 128>>>();
    k_scat<<<NBLK, 1024>>>();
    k_fill<<<(NE + 255) / 256, 256>>>(src, dst);

    // layer 1: tf32x3 mma.sync GEMM
    k_wsplit<<<(H1 * F_IN + 255) / 256, 256>>>(W1);
    k_gemm1_mma<<<(NN + 127) / 128, 256, G1_SMEM>>>(x, p_h1lin);
    k_agg128<<<(NN * 32 + 255) / 256, 256>>>(b1);

    // layer 2
    sgemm<128, 64, 16, 8, 4><<<dim3((NN + 127) / 128, 1), 256>>>(p_h1, W2, p_h2lin, NN, H2, H1);
    k_agg64<<<(NN * 32 + 255) / 256, 256>>>(b2);

    // scorer
    k_score_mma<<<(NL + 127) / 128, 256, SC_SMEM>>>(la, lb, fcW1, fcb1, fcW2, fcb2, out);
}

// round 5
// speedup vs baseline: 1.3842x; 1.1612x over previous
#include <cuda_runtime.h>
#include <cuda_fp16.h>
#include <math.h>
#include <stdint.h>

#define NN 100000
#define NE 3200000
#define NL 1000000
#define F_IN 512
#define H1 128
#define H2 64
#define NBLK ((NN + 1023) / 1024)

// ---------------- scratch (static device globals; no allocs) ----------------
__device__ __half g_h1lin_h[(size_t)NN * H1];   // fp16 pre-agg layer1
__device__ float  g_h1   [(size_t)NN * H1];     // fp32 post-relu layer1
__device__ __half g_h2lin_h[(size_t)NN * H2];   // fp16 pre-agg layer2
__device__ float  g_h2   [(size_t)NN * H2];     // fp32 post-relu layer2
__device__ float  g_dinv [NN];
__device__ int    g_count[NN];
__device__ int    g_rowptr[NN + 1];
__device__ int    g_cursor[NN];
__device__ int    g_csr  [NE];
__device__ int    g_bsum [NBLK];
__device__ int    g_bpre [NBLK];
__device__ float  g_whT[(size_t)H1 * F_IN];     // W1^T hi [128][512]
__device__ float  g_wlT[(size_t)H1 * F_IN];     // W1^T lo
__device__ float  g_w2hT[(size_t)H2 * H1];      // W2^T hi [64][128]
__device__ float  g_w2lT[(size_t)H2 * H1];      // W2^T lo

// ---------------- helpers ----------------
__device__ __forceinline__ uint32_t smem_u32(const void* p) {
    uint32_t a;
    asm("{ .reg .u64 t; cvta.to.shared.u64 t, %1; cvt.u32.u64 %0, t; }" : "=r"(a) : "l"(p));
    return a;
}
__device__ __forceinline__ float tf32r(float x) {
    uint32_t u;
    asm("cvt.rna.tf32.f32 %0, %1;" : "=r"(u) : "f"(x));
    return __uint_as_float(u);
}
#define MMA(c, a, b) \
    asm volatile("mma.sync.aligned.m16n8k8.row.col.f32.tf32.tf32.f32 " \
                 "{%0,%1,%2,%3}, {%4,%5,%6,%7}, {%8,%9}, {%0,%1,%2,%3};" \
                 : "+f"((c)[0]), "+f"((c)[1]), "+f"((c)[2]), "+f"((c)[3]) \
                 : "r"((a)[0]), "r"((a)[1]), "r"((a)[2]), "r"((a)[3]), \
                   "r"((b)[0]), "r"((b)[1]))

// ---------------- CSR build ----------------
__global__ void k_zero_count() {
    int i = blockIdx.x * blockDim.x + threadIdx.x;
    if (i < NN) g_count[i] = 0;
}
__global__ void k_hist(const int* __restrict__ dst) {
    int i = blockIdx.x * blockDim.x + threadIdx.x;
    if (i < NE) atomicAdd(&g_count[dst[i]], 1);
}
__global__ void k_dinv() {
    int i = blockIdx.x * blockDim.x + threadIdx.x;
    if (i < NN) g_dinv[i] = rsqrtf((float)(g_count[i] + 1));
}
__global__ void k_bsum() {
    __shared__ int ws[32];
    int t = threadIdx.x, lane = t & 31, wid = t >> 5;
    int i = blockIdx.x * 1024 + t;
    int v = (i < NN) ? g_count[i] : 0;
    #pragma unroll
    for (int o = 16; o; o >>= 1) v += __shfl_down_sync(0xffffffffu, v, o);
    if (lane == 0) ws[wid] = v;
    __syncthreads();
    if (wid == 0) {
        int x = ws[lane];
        #pragma unroll
        for (int o = 16; o; o >>= 1) x += __shfl_down_sync(0xffffffffu, x, o);
        if (lane == 0) g_bsum[blockIdx.x] = x;
    }
}
__global__ void k_bscan() {
    __shared__ int ws[4];
    int t = threadIdx.x, lane = t & 31, wid = t >> 5;
    int v = (t < NBLK) ? g_bsum[t] : 0;
    int x = v;
    #pragma unroll
    for (int o = 1; o < 32; o <<= 1) {
        int y = __shfl_up_sync(0xffffffffu, x, o);
        if (lane >= o) x += y;
    }
    if (lane == 31) ws[wid] = x;
    __syncthreads();
    int add = 0;
    for (int w = 0; w < wid; w++) add += ws[w];
    int incl = x + add;
    if (t < NBLK) g_bpre[t] = incl - v;
    if (t == 127) g_rowptr[NN] = incl;
}
__global__ void k_scat() {
    __shared__ int ws[32];
    int t = threadIdx.x, lane = t & 31, wid = t >> 5;
    int i = blockIdx.x * 1024 + t;
    int v = (i < NN) ? g_count[i] : 0;
    int x = v;
    #pragma unroll
    for (int o = 1; o < 32; o <<= 1) {
        int y = __shfl_up_sync(0xffffffffu, x, o);
        if (lane >= o) x += y;
    }
    if (lane == 31) ws[wid] = x;
    __syncthreads();
    if (wid == 0) {
        int w = ws[lane];
        #pragma unroll
        for (int o = 1; o < 32; o <<= 1) {
            int y = __shfl_up_sync(0xffffffffu, w, o);
            if (lane >= o) w += y;
        }
        ws[lane] = w;
    }
    __syncthreads();
    int excl = g_bpre[blockIdx.x] + (wid ? ws[wid - 1] : 0) + x - v;
    if (i < NN) { g_rowptr[i] = excl; g_cursor[i] = excl; }
}
__global__ void k_fill(const int* __restrict__ src, const int* __restrict__ dst) {
    int i = blockIdx.x * blockDim.x + threadIdx.x;
    if (i < NE) {
        int p = atomicAdd(&g_cursor[dst[i]], 1);
        g_csr[p] = src[i];
    }
}

// ---------------- weight transpose + tf32 hi/lo splits ----------------
__global__ void k_wsplit(const float* __restrict__ W1) {
    int i = blockIdx.x * blockDim.x + threadIdx.x;
    if (i < H1 * F_IN) {
        int n = i & (H1 - 1);
        int k = i >> 7;
        float w = W1[(size_t)k * H1 + n];
        float h = tf32r(w);
        g_whT[(size_t)n * F_IN + k] = h;
        g_wlT[(size_t)n * F_IN + k] = tf32r(w - h);
    }
}
__global__ void k_wsplit2(const float* __restrict__ W2) {
    int i = blockIdx.x * blockDim.x + threadIdx.x;
    if (i < H2 * H1) {
        int n = i & (H2 - 1);
        int k = i >> 6;
        float w = W2[(size_t)k * H2 + n];
        float h = tf32r(w);
        g_w2hT[(size_t)n * H1 + k] = h;
        g_w2lT[(size_t)n * H1 + k] = tf32r(w - h);
    }
}

// ---------------- GEMM1 via mma.sync tf32x3: h1lin[100000,128] = A @ W1 ----------------
#define G1_STAGE_F 18432
#define G1_SMEM (2 * G1_STAGE_F * 4)

__global__ void __launch_bounds__(256, 1)
k_gemm1_mma(const float* __restrict__ A) {
    extern __shared__ float sm[];
    const int tid = threadIdx.x, lane = tid & 31, wid = tid >> 5;
    const int rowBase = blockIdx.x * 128;
    const int wm = (wid >> 1) * 32, wn = (wid & 1) * 64;

    float acc[2][8][4];
    #pragma unroll
    for (int mt = 0; mt < 2; mt++)
        #pragma unroll
        for (int nt = 0; nt < 8; nt++)
            #pragma unroll
            for (int i = 0; i < 4; i++) acc[mt][nt][i] = 0.f;

    float4 pa[4];
    auto ldgA = [&](int kt) {
        #pragma unroll
        for (int l = 0; l < 4; l++) {
            int f = tid + l * 256;
            int row = f >> 3, c4 = f & 7;
            int gr = rowBase + row;
            pa[l] = (gr < NN) ? *(const float4*)&A[(size_t)gr * F_IN + kt + c4 * 4]
                              : make_float4(0.f, 0.f, 0.f, 0.f);
        }
    };
    auto stsA = [&](float* buf) {
        #pragma unroll
        for (int l = 0; l < 4; l++) {
            int f = tid + l * 256;
            int row = f >> 3, c4 = f & 7;
            float4 v = pa[l];
            float hx = tf32r(v.x), hy = tf32r(v.y), hz = tf32r(v.z), hw = tf32r(v.w);
            *(float4*)&buf[row * 36 + c4 * 4]        = make_float4(hx, hy, hz, hw);
            *(float4*)&buf[4608 + row * 36 + c4 * 4] =
                make_float4(tf32r(v.x - hx), tf32r(v.y - hy), tf32r(v.z - hz), tf32r(v.w - hw));
        }
    };
    auto cpB = [&](int kt, float* buf) {
        #pragma unroll
        for (int l = 0; l < 8; l++) {
            int idx = tid + l * 256;
            int sel = idx >> 10;
            int j = idx & 1023;
            int r = j >> 3, c4 = j & 7;
            const float* g = (sel ? g_wlT : g_whT) + (size_t)r * F_IN + kt + c4 * 4;
            float* s = buf + 9216 + sel * 4608 + r * 36 + c4 * 4;
            uint32_t sa = smem_u32(s);
            asm volatile("cp.async.cg.shared.global [%0], [%1], 16;\n" :: "r"(sa), "l"(g));
        }
        asm volatile("cp.async.commit_group;\n");
    };

    ldgA(0);
    cpB(0, sm);
    stsA(sm);
    asm volatile("cp.async.wait_group 0;\n");
    __syncthreads();

    for (int s = 0; s < 16; s++) {
        float* cur = sm + (s & 1) * G1_STAGE_F;
        float* nxt = sm + ((s + 1) & 1) * G1_STAGE_F;
        if (s + 1 < 16) { cpB((s + 1) * 32, nxt); ldgA((s + 1) * 32); }

        const float* Ah = cur;
        const float* Al = cur + 4608;
        const float* Bh = cur + 9216;
        const float* Bl = cur + 13824;
        const int rA = wm + (lane >> 2);
        const int cA = lane & 3;
        const int cB = lane >> 2;
        const int rB = lane & 3;

        #pragma unroll
        for (int ks = 0; ks < 4; ks++) {
            int kb = ks * 8;
            uint32_t ah[2][4], al[2][4];
            #pragma unroll
            for (int mt = 0; mt < 2; mt++) {
                int rr = rA + mt * 16;
                ah[mt][0] = __float_as_uint(Ah[rr * 36 + kb + cA]);
                ah[mt][1] = __float_as_uint(Ah[(rr + 8) * 36 + kb + cA]);
                ah[mt][2] = __float_as_uint(Ah[rr * 36 + kb + cA + 4]);
                ah[mt][3] = __float_as_uint(Ah[(rr + 8) * 36 + kb + cA + 4]);
                al[mt][0] = __float_as_uint(Al[rr * 36 + kb + cA]);
                al[mt][1] = __float_as_uint(Al[(rr + 8) * 36 + kb + cA]);
                al[mt][2] = __float_as_uint(Al[rr * 36 + kb + cA + 4]);
                al[mt][3] = __float_as_uint(Al[(rr + 8) * 36 + kb + cA + 4]);
            }
            uint32_t bh[8][2], bl[8][2];
            #pragma unroll
            for (int nt = 0; nt < 8; nt++) {
                int cc = wn + nt * 8 + cB;
                bh[nt][0] = __float_as_uint(Bh[cc * 36 + kb + rB]);
                bh[nt][1] = __float_as_uint(Bh[cc * 36 + kb + rB + 4]);
                bl[nt][0] = __float_as_uint(Bl[cc * 36 + kb + rB]);
                bl[nt][1] = __float_as_uint(Bl[cc * 36 + kb + rB + 4]);
            }
            #pragma unroll
            for (int mt = 0; mt < 2; mt++)
                #pragma unroll
                for (int nt = 0; nt < 8; nt++) {
                    MMA(acc[mt][nt], ah[mt], bh[nt]);
                    MMA(acc[mt][nt], al[mt], bh[nt]);
                    MMA(acc[mt][nt], ah[mt], bl[nt]);
                }
        }
        if (s + 1 < 16) { stsA(nxt); asm volatile("cp.async.wait_group 0;\n"); }
        __syncthreads();
    }

    #pragma unroll
    for (int mt = 0; mt < 2; mt++) {
        int row = rowBase + wm + mt * 16 + (lane >> 2);
        #pragma unroll
        for (int nt = 0; nt < 8; nt++) {
            int col = wn + nt * 8 + (lane & 3) * 2;
            if (row < NN)
                *(__half2*)&g_h1lin_h[(size_t)row * H1 + col] =
                    __floats2half2_rn(acc[mt][nt][0], acc[mt][nt][1]);
            if (row + 8 < NN)
                *(__half2*)&g_h1lin_h[(size_t)(row + 8) * H1 + col] =
                    __floats2half2_rn(acc[mt][nt][2], acc[mt][nt][3]);
        }
    }
}

// ---------------- GEMM2 via mma.sync tf32x3: h2lin[100000,64] = g_h1 @ W2 ----------------
// stage floats: Ah@0(4608) Al@4608 Bh@9216(2304) Bl@11520 -> 13824; x2 buffers
#define G2_STAGE_F 13824
#define G2_SMEM (2 * G2_STAGE_F * 4)

__global__ void __launch_bounds__(256, 1)
k_gemm2_mma() {
    extern __shared__ float sm[];
    const int tid = threadIdx.x, lane = tid & 31, wid = tid >> 5;
    const int rowBase = blockIdx.x * 128;
    const int wm = wid * 16;

    float acc[8][4];
    #pragma unroll
    for (int nt = 0; nt < 8; nt++)
        #pragma unroll
        for (int i = 0; i < 4; i++) acc[nt][i] = 0.f;

    float4 pa[4];
    auto ldgA = [&](int kt) {
        #pragma unroll
        for (int l = 0; l < 4; l++) {
            int f = tid + l * 256;
            int row = f >> 3, c4 = f & 7;
            int gr = rowBase + row;
            pa[l] = (gr < NN) ? *(const float4*)&g_h1[(size_t)gr * H1 + kt + c4 * 4]
                              : make_float4(0.f, 0.f, 0.f, 0.f);
        }
    };
    auto stsA = [&](float* buf) {
        #pragma unroll
        for (int l = 0; l < 4; l++) {
            int f = tid + l * 256;
            int row = f >> 3, c4 = f & 7;
            float4 v = pa[l];
            float hx = tf32r(v.x), hy = tf32r(v.y), hz = tf32r(v.z), hw = tf32r(v.w);
            *(float4*)&buf[row * 36 + c4 * 4]        = make_float4(hx, hy, hz, hw);
            *(float4*)&buf[4608 + row * 36 + c4 * 4] =
                make_float4(tf32r(v.x - hx), tf32r(v.y - hy), tf32r(v.z - hz), tf32r(v.w - hw));
        }
    };
    auto cpB = [&](int kt, float* buf) {
        #pragma unroll
        for (int l = 0; l < 4; l++) {
            int idx = tid + l * 256;        // 1024 float4 = 2 x (64 rows x 8)
            int sel = idx >> 9;
            int j = idx & 511;
            int r = j >> 3, c4 = j & 7;
            const float* g = (sel ? g_w2lT : g_w2hT) + (size_t)r * H1 + kt + c4 * 4;
            float* s = buf + 9216 + sel * 2304 + r * 36 + c4 * 4;
            uint32_t sa = smem_u32(s);
            asm volatile("cp.async.cg.shared.global [%0], [%1], 16;\n" :: "r"(sa), "l"(g));
        }
        asm volatile("cp.async.commit_group;\n");
    };

    ldgA(0);
    cpB(0, sm);
    stsA(sm);
    asm volatile("cp.async.wait_group 0;\n");
    __syncthreads();

    for (int s = 0; s < 4; s++) {
        float* cur = sm + (s & 1) * G2_STAGE_F;
        float* nxt = sm + ((s + 1) & 1) * G2_STAGE_F;
        if (s + 1 < 4) { cpB((s + 1) * 32, nxt); ldgA((s + 1) * 32); }

        const float* Ah = cur;
        const float* Al = cur + 4608;
        const float* Bh = cur + 9216;
        const float* Bl = cur + 11520;
        const int rA = wm + (lane >> 2);
        const int cA = lane & 3;
        const int cB = lane >> 2;
        const int rB = lane & 3;

        #pragma unroll
        for (int ks = 0; ks < 4; ks++) {
            int kb = ks * 8;
            uint32_t ah[4], al[4];
            ah[0] = __float_as_uint(Ah[rA * 36 + kb + cA]);
            ah[1] = __float_as_uint(Ah[(rA + 8) * 36 + kb + cA]);
            ah[2] = __float_as_uint(Ah[rA * 36 + kb + cA + 4]);
            ah[3] = __float_as_uint(Ah[(rA + 8) * 36 + kb + cA + 4]);
            al[0] = __float_as_uint(Al[rA * 36 + kb + cA]);
            al[1] = __float_as_uint(Al[(rA + 8) * 36 + kb + cA]);
            al[2] = __float_as_uint(Al[rA * 36 + kb + cA + 4]);
            al[3] = __float_as_uint(Al[(rA + 8) * 36 + kb + cA + 4]);
            #pragma unroll
            for (int nt = 0; nt < 8; nt++) {
                int cc = nt * 8 + cB;
                uint32_t bh[2], bl[2];
                bh[0] = __float_as_uint(Bh[cc * 36 + kb + rB]);
                bh[1] = __float_as_uint(Bh[cc * 36 + kb + rB + 4]);
                bl[0] = __float_as_uint(Bl[cc * 36 + kb + rB]);
                bl[1] = __float_as_uint(Bl[cc * 36 + kb + rB + 4]);
                MMA(acc[nt], ah, bh);
                MMA(acc[nt], al, bh);
                MMA(acc[nt], ah, bl);
            }
        }
        if (s + 1 < 4) { stsA(nxt); asm volatile("cp.async.wait_group 0;\n"); }
        __syncthreads();
    }

    int row = rowBase + wm + (lane >> 2);
    #pragma unroll
    for (int nt = 0; nt < 8; nt++) {
        int col = nt * 8 + (lane & 3) * 2;
        if (row < NN)
            *(__half2*)&g_h2lin_h[(size_t)row * H2 + col] =
                __floats2half2_rn(acc[nt][0], acc[nt][1]);
        if (row + 8 < NN)
            *(__half2*)&g_h2lin_h[(size_t)(row + 8) * H2 + col] =
                __floats2half2_rn(acc[nt][2], acc[nt][3]);
    }
}

// ---------------- gather aggregation (fp16 in, fp32 accum) ----------------
__global__ void k_agg128(const float* __restrict__ bias) {
    int gw = (blockIdx.x * blockDim.x + threadIdx.x) >> 5;
    int lane = threadIdx.x & 31;
    if (gw >= NN) return;
    float dd = g_dinv[gw];
    float w0 = dd * dd;
    uint2 raw = *(const uint2*)&g_h1lin_h[(size_t)gw * H1 + lane * 4];
    float2 f0 = __half22float2(*(__half2*)&raw.x);
    float2 f1 = __half22float2(*(__half2*)&raw.y);
    float4 acc = make_float4(f0.x * w0, f0.y * w0, f1.x * w0, f1.y * w0);
    int s0 = g_rowptr[gw], s1 = g_rowptr[gw + 1];
    for (int base = s0; base < s1; base += 32) {
        int rem = s1 - base;
        int s = 0; float nm = 0.f;
        if (lane < rem) { s = g_csr[base + lane]; nm = dd * g_dinv[s]; }
        int cnt = rem < 32 ? rem : 32;
        for (int j = 0; j < cnt; j++) {
            int ss = __shfl_sync(0xffffffffu, s, j);
            float nn = __shfl_sync(0xffffffffu, nm, j);
            uint2 r2 = *(const uint2*)&g_h1lin_h[(size_t)ss * H1 + lane * 4];
            float2 a0 = __half22float2(*(__half2*)&r2.x);
            float2 a1 = __half22float2(*(__half2*)&r2.y);
            acc.x += nn * a0.x; acc.y += nn * a0.y;
            acc.z += nn * a1.x; acc.w += nn * a1.y;
        }
    }
    float4 bb = ((const float4*)bias)[lane];
    float4 r;
    r.x = fmaxf(acc.x + bb.x, 0.f);
    r.y = fmaxf(acc.y + bb.y, 0.f);
    r.z = fmaxf(acc.z + bb.z, 0.f);
    r.w = fmaxf(acc.w + bb.w, 0.f);
    ((float4*)g_h1)[(size_t)gw * 32 + lane] = r;
}

__global__ void k_agg64(const float* __restrict__ bias) {
    int gw = (blockIdx.x * blockDim.x + threadIdx.x) >> 5;
    int lane = threadIdx.x & 31;
    if (gw >= NN) return;
    float dd = g_dinv[gw];
    float w0 = dd * dd;
    float2 f0 = __half22float2(*(const __half2*)&g_h2lin_h[(size_t)gw * H2 + lane * 2]);
    float2 acc = make_float2(f0.x * w0, f0.y * w0);
    int s0 = g_rowptr[gw], s1 = g_rowptr[gw + 1];
    for (int base = s0; base < s1; base += 32) {
        int rem = s1 - base;
        int s = 0; float nm = 0.f;
        if (lane < rem) { s = g_csr[base + lane]; nm = dd * g_dinv[s]; }
        int cnt = rem < 32 ? rem : 32;
        for (int j = 0; j < cnt; j++) {
            int ss = __shfl_sync(0xffffffffu, s, j);
            float nn = __shfl_sync(0xffffffffu, nm, j);
            float2 hv = __half22float2(*(const __half2*)&g_h2lin_h[(size_t)ss * H2 + lane * 2]);
            acc.x += nn * hv.x; acc.y += nn * hv.y;
        }
    }
    float2 bb = ((const float2*)bias)[lane];
    float2 r;
    r.x = fmaxf(acc.x + bb.x, 0.f);
    r.y = fmaxf(acc.y + bb.y, 0.f);
    ((float2*)g_h2)[(size_t)gw * 32 + lane] = r;
}

// ---------------- edge scorer via mma.sync tf32x3, register epilogue ----------------
// smem floats: Th@0(9216) Tl@9216 Wh@18432(4608) Wl@23040 w2s@27648(128) b1s@27776(64)
#define SC_SMEM (27840 * 4)

__global__ void __launch_bounds__(256, 1)
k_score_mma(const int* __restrict__ la, const int* __restrict__ lb,
            const float* __restrict__ fcW1, const float* __restrict__ fcb1,
            const float* __restrict__ fcW2, const float* __restrict__ fcb2,
            float* __restrict__ out) {
    extern __shared__ float sm[];
    float* Th = sm;
    float* Tl = sm + 9216;
    float* Wh = sm + 18432;
    float* Wl = sm + 23040;
    float* w2s = sm + 27648;
    float* b1s = sm + 27776;
    const int tid = threadIdx.x, lane = tid & 31, wid = tid >> 5;
    const int e0 = blockIdx.x * 128;

    #pragma unroll
    for (int l = 0; l < 16; l++) {
        int idx = tid + l * 256;
        float w = fcW1[idx];
        float h = tf32r(w);
        Wh[(idx >> 6) * 72 + (idx & 63)] = h;
        Wl[(idx >> 6) * 72 + (idx & 63)] = tf32r(w - h);
    }
    if (tid < 128) w2s[tid] = fcW2[tid];
    if (tid < 64)  b1s[tid] = fcb1[tid];

    #pragma unroll
    for (int l = 0; l < 8; l++) {
        int idx = tid + l * 256;
        int e = idx >> 4, c4 = idx & 15;
        int eg = e0 + e;
        if (eg >= NL) eg = NL - 1;
        int a = la[eg], b = lb[eg];
        float4 va = *(const float4*)&g_h2[(size_t)a * H2 + c4 * 4];
        float4 vb = *(const float4*)&g_h2[(size_t)b * H2 + c4 * 4];
        float px = va.x * vb.x, py = va.y * vb.y, pz = va.z * vb.z, pw = va.w * vb.w;
        float hx = tf32r(px), hy = tf32r(py), hz = tf32r(pz), hw = tf32r(pw);
        *(float4*)&Th[e * 72 + c4 * 4] = make_float4(hx, hy, hz, hw);
        *(float4*)&Tl[e * 72 + c4 * 4] =
            make_float4(tf32r(px - hx), tf32r(py - hy), tf32r(pz - hz), tf32r(pw - hw));
    }
    __syncthreads();

    float acc[8][4];
    #pragma unroll
    for (int nt = 0; nt < 8; nt++)
        #pragma unroll
        for (int i = 0; i < 4; i++) acc[nt][i] = 0.f;

    const int rA = wid * 16 + (lane >> 2), cA = lane & 3;
    const int cB = lane >> 2, rB = lane & 3;
    #pragma unroll
    for (int ks = 0; ks < 8; ks++) {
        int kb = ks * 8;
        uint32_t ah[4], al[4];
        ah[0] = __float_as_uint(Th[rA * 72 + kb + cA]);
        ah[1] = __float_as_uint(Th[(rA + 8) * 72 + kb + cA]);
        ah[2] = __float_as_uint(Th[rA * 72 + kb + cA + 4]);
        ah[3] = __float_as_uint(Th[(rA + 8) * 72 + kb + cA + 4]);
        al[0] = __float_as_uint(Tl[rA * 72 + kb + cA]);
        al[1] = __float_as_uint(Tl[(rA + 8) * 72 + kb + cA]);
        al[2] = __float_as_uint(Tl[rA * 72 + kb + cA + 4]);
        al[3] = __float_as_uint(Tl[(rA + 8) * 72 + kb + cA + 4]);
        #pragma unroll
        for (int nt = 0; nt < 8; nt++) {
            int cc = nt * 8 + cB;
            uint32_t bh[2], bl[2];
            bh[0] = __float_as_uint(Wh[(kb + rB) * 72 + cc]);
            bh[1] = __float_as_uint(Wh[(kb + rB + 4) * 72 + cc]);
            bl[0] = __float_as_uint(Wl[(kb + rB) * 72 + cc]);
            bl[1] = __float_as_uint(Wl[(kb + rB + 4) * 72 + cc]);
            MMA(acc[nt], ah, bh);
            MMA(acc[nt], al, bh);
            MMA(acc[nt], ah, bl);
        }
    }

    // second layer in registers
    float p00 = 0.f, p01 = 0.f, p10 = 0.f, p11 = 0.f;
    #pragma unroll
    for (int nt = 0; nt < 8; nt++) {
        int col = nt * 8 + (lane & 3) * 2;
        float4 w2a = *(float4*)&w2s[col * 2];
        float b0v = b1s[col], b1v = b1s[col + 1];
        float u0 = fmaxf(acc[nt][0] + b0v, 0.f);
        float u1 = fmaxf(acc[nt][1] + b1v, 0.f);
        float u2 = fmaxf(acc[nt][2] + b0v, 0.f);
        float u3 = fmaxf(acc[nt][3] + b1v, 0.f);
        p00 += u0 * w2a.x + u1 * w2a.z;
        p01 += u0 * w2a.y + u1 * w2a.w;
        p10 += u2 * w2a.x + u3 * w2a.z;
        p11 += u2 * w2a.y + u3 * w2a.w;
    }
    #pragma unroll
    for (int off = 1; off <= 2; off <<= 1) {
        p00 += __shfl_xor_sync(0xffffffffu, p00, off);
        p01 += __shfl_xor_sync(0xffffffffu, p01, off);
        p10 += __shfl_xor_sync(0xffffffffu, p10, off);
        p11 += __shfl_xor_sync(0xffffffffu, p11, off);
    }
    if ((lane & 3) == 0) {
        float c0 = fcb2[0], c1 = fcb2[1];
        int e = e0 + wid * 16 + (lane >> 2);
        if (e < NL)     *(float2*)&out[(size_t)e * 2]       = make_float2(p00 + c0, p01 + c1);
        if (e + 8 < NL) *(float2*)&out[(size_t)(e + 8) * 2] = make_float2(p10 + c0, p11 + c1);
    }
}

// ---------------- launch ----------------
extern "C" void kernel_launch(void* const* d_in, const int* in_sizes, int n_in,
                              void* d_out, int out_size) {
    const float* x    = (const float*)d_in[0];
    const float* W1   = (const float*)d_in[1];
    const float* b1   = (const float*)d_in[2];
    const float* W2   = (const float*)d_in[3];
    const float* b2   = (const float*)d_in[4];
    const float* fcW1 = (const float*)d_in[5];
    const float* fcb1 = (const float*)d_in[6];
    const float* fcW2 = (const float*)d_in[7];
    const float* fcb2 = (const float*)d_in[8];
    const int* eidx = (const int*)d_in[9];
    const int* elab = (const int*)d_in[10];
    const int* src = eidx;
    const int* dst = eidx + NE;
    const int* la = elab;
    const int* lb = elab + NL;
    float* out = (float*)d_out;

    static int attr_done = 0;
    if (!attr_done) {
        cudaFuncSetAttribute(k_gemm1_mma, cudaFuncAttributeMaxDynamicSharedMemorySize, G1_SMEM);
        cudaFuncSetAttribute(k_gemm2_mma, cudaFuncAttributeMaxDynamicSharedMemorySize, G2_SMEM);
        cudaFuncSetAttribute(k_score_mma, cudaFuncAttributeMaxDynamicSharedMemorySize, SC_SMEM);
        attr_done = 1;
    }

    // CSR build + degrees
    k_zero_count<<<(NN + 255) / 256, 256>>>();
    k_hist<<<(NE + 255) / 256, 256>>>(dst);
    k_dinv<<<(NN + 255) / 256, 256>>>();
    k_bsum<<<NBLK, 1024>>>();
    k_bscan<<<1, 128>>>();
    k_scat<<<NBLK, 1024>>>();
    k_fill<<<(NE + 255) / 256, 256>>>(src, dst);

    // layer 1
    k_wsplit<<<(H1 * F_IN + 255) / 256, 256>>>(W1);
    k_gemm1_mma<<<(NN + 127) / 128, 256, G1_SMEM>>>(x);
    k_agg128<<<(NN * 32 + 255) / 256, 256>>>(b1);

    // layer 2
    k_wsplit2<<<(H2 * H1 + 255) / 256, 256>>>(W2);
    k_gemm2_mma<<<(NN + 127) / 128, 256, G2_SMEM>>>();
    k_agg64<<<(NN * 32 + 255) / 256, 256>>>(b2);

    // scorer
    k_score_mma<<<(NL + 127) / 128, 256, SC_SMEM>>>(la, lb, fcW1, fcb1, fcW2, fcb2, out);
}

// round 6
// speedup vs baseline: 1.9623x; 1.4177x over previous
#include <cuda_runtime.h>
#include <cuda_fp16.h>
#include <math.h>
#include <stdint.h>

#define NN 100000
#define NE 3200000
#define NL 1000000
#define F_IN 512
#define H1 128
#define H2 64
#define NBLK ((NN + 1023) / 1024)

// ---------------- scratch (static device globals; no allocs) ----------------
__device__ __half g_h1lin_h[(size_t)NN * H1];   // fp16 pre-agg layer1
__device__ __half g_h1_h  [(size_t)NN * H1];    // fp16 post-relu layer1
__device__ __half g_h2lin_h[(size_t)NN * H2];   // fp16 pre-agg layer2
__device__ __half g_h2_h  [(size_t)NN * H2];    // fp16 post-relu layer2
__device__ float  g_dinv [NN];
__device__ int    g_count[NN];
__device__ int    g_rowptr[NN + 1];
__device__ int    g_cursor[NN];
__device__ int    g_csr  [NE];
__device__ int    g_bsum [NBLK];
__device__ int    g_bpre [NBLK];
__device__ __half g_w1h[(size_t)H1 * F_IN];     // W1^T hi [128][512] fp16
__device__ __half g_w1l[(size_t)H1 * F_IN];     // W1^T lo
__device__ __half g_w2h[(size_t)H2 * H1];       // W2^T hi [64][128] fp16
__device__ __half g_w2l[(size_t)H2 * H1];       // W2^T lo

// ---------------- helpers ----------------
__device__ __forceinline__ uint32_t smem_u32(const void* p) {
    uint32_t a;
    asm("{ .reg .u64 t; cvta.to.shared.u64 t, %1; cvt.u32.u64 %0, t; }" : "=r"(a) : "l"(p));
    return a;
}
// m16n8k16 fp16 mma, fp32 accumulate
#define HMMA(c, a, b) \
    asm volatile("mma.sync.aligned.m16n8k16.row.col.f32.f16.f16.f32 " \
                 "{%0,%1,%2,%3}, {%4,%5,%6,%7}, {%8,%9}, {%0,%1,%2,%3};" \
                 : "+f"((c)[0]), "+f"((c)[1]), "+f"((c)[2]), "+f"((c)[3]) \
                 : "r"((a)[0]), "r"((a)[1]), "r"((a)[2]), "r"((a)[3]), \
                   "r"((b)[0]), "r"((b)[1]))

// ---------------- CSR build ----------------
__global__ void k_zero_count() {
    int i = blockIdx.x * blockDim.x + threadIdx.x;
    if (i < NN) g_count[i] = 0;
}
__global__ void k_hist(const int* __restrict__ dst) {
    int i = blockIdx.x * blockDim.x + threadIdx.x;
    if (i < NE) atomicAdd(&g_count[dst[i]], 1);
}
__global__ void k_dinv() {
    int i = blockIdx.x * blockDim.x + threadIdx.x;
    if (i < NN) g_dinv[i] = rsqrtf((float)(g_count[i] + 1));
}
__global__ void k_bsum() {
    __shared__ int ws[32];
    int t = threadIdx.x, lane = t & 31, wid = t >> 5;
    int i = blockIdx.x * 1024 + t;
    int v = (i < NN) ? g_count[i] : 0;
    #pragma unroll
    for (int o = 16; o; o >>= 1) v += __shfl_down_sync(0xffffffffu, v, o);
    if (lane == 0) ws[wid] = v;
    __syncthreads();
    if (wid == 0) {
        int x = ws[lane];
        #pragma unroll
        for (int o = 16; o; o >>= 1) x += __shfl_down_sync(0xffffffffu, x, o);
        if (lane == 0) g_bsum[blockIdx.x] = x;
    }
}
__global__ void k_bscan() {
    __shared__ int ws[4];
    int t = threadIdx.x, lane = t & 31, wid = t >> 5;
    int v = (t < NBLK) ? g_bsum[t] : 0;
    int x = v;
    #pragma unroll
    for (int o = 1; o < 32; o <<= 1) {
        int y = __shfl_up_sync(0xffffffffu, x, o);
        if (lane >= o) x += y;
    }
    if (lane == 31) ws[wid] = x;
    __syncthreads();
    int add = 0;
    for (int w = 0; w < wid; w++) add += ws[w];
    int incl = x + add;
    if (t < NBLK) g_bpre[t] = incl - v;
    if (t == 127) g_rowptr[NN] = incl;
}
__global__ void k_scat() {
    __shared__ int ws[32];
    int t = threadIdx.x, lane = t & 31, wid = t >> 5;
    int i = blockIdx.x * 1024 + t;
    int v = (i < NN) ? g_count[i] : 0;
    int x = v;
    #pragma unroll
    for (int o = 1; o < 32; o <<= 1) {
        int y = __shfl_up_sync(0xffffffffu, x, o);
        if (lane >= o) x += y;
    }
    if (lane == 31) ws[wid] = x;
    __syncthreads();
    if (wid == 0) {
        int w = ws[lane];
        #pragma unroll
        for (int o = 1; o < 32; o <<= 1) {
            int y = __shfl_up_sync(0xffffffffu, w, o);
            if (lane >= o) w += y;
        }
        ws[lane] = w;
    }
    __syncthreads();
    int excl = g_bpre[blockIdx.x] + (wid ? ws[wid - 1] : 0) + x - v;
    if (i < NN) { g_rowptr[i] = excl; g_cursor[i] = excl; }
}
__global__ void k_fill(const int* __restrict__ src, const int* __restrict__ dst) {
    int i = blockIdx.x * blockDim.x + threadIdx.x;
    if (i < NE) {
        int p = atomicAdd(&g_cursor[dst[i]], 1);
        g_csr[p] = src[i];
    }
}

// ---------------- weight transpose + fp16 hi/lo splits ----------------
__global__ void k_wsplit(const float* __restrict__ W1) {
    int i = blockIdx.x * blockDim.x + threadIdx.x;
    if (i < H1 * F_IN) {
        int n = i & (H1 - 1);
        int k = i >> 7;
        float w = W1[(size_t)k * H1 + n];
        __half h = __float2half_rn(w);
        g_w1h[(size_t)n * F_IN + k] = h;
        g_w1l[(size_t)n * F_IN + k] = __float2half_rn(w - __half2float(h));
    }
}
__global__ void k_wsplit2(const float* __restrict__ W2) {
    int i = blockIdx.x * blockDim.x + threadIdx.x;
    if (i < H2 * H1) {
        int n = i & (H2 - 1);
        int k = i >> 6;
        float w = W2[(size_t)k * H2 + n];
        __half h = __float2half_rn(w);
        g_w2h[(size_t)n * H1 + k] = h;
        g_w2l[(size_t)n * H1 + k] = __float2half_rn(w - __half2float(h));
    }
}

// ---------------- GEMM1 fp16x3 HMMA: h1lin[100000,128] = x @ W1 ----------------
// stage (halves, stride 40/row): Ah@0(5120) Al@5120 Bh@10240(5120) Bl@15360 -> 20480
#define G1_STAGE_H 20480
#define G1_SMEM (2 * G1_STAGE_H * 2)

__global__ void __launch_bounds__(256, 1)
k_gemm1_mma(const float* __restrict__ A) {
    extern __shared__ __half smh[];
    const int tid = threadIdx.x, lane = tid & 31, wid = tid >> 5;
    const int gid = lane >> 2, tq = lane & 3;
    const int rowBase = blockIdx.x * 128;
    const int wm = (wid >> 1) * 32, wn = (wid & 1) * 64;

    float acc[2][8][4];
    #pragma unroll
    for (int mt = 0; mt < 2; mt++)
        #pragma unroll
        for (int nt = 0; nt < 8; nt++)
            #pragma unroll
            for (int i = 0; i < 4; i++) acc[mt][nt][i] = 0.f;

    float4 pa[4];
    auto ldgA = [&](int kt) {
        #pragma unroll
        for (int l = 0; l < 4; l++) {
            int f = tid + l * 256;
            int row = f >> 3, c4 = f & 7;
            int gr = rowBase + row;
            pa[l] = (gr < NN) ? *(const float4*)&A[(size_t)gr * F_IN + kt + c4 * 4]
                              : make_float4(0.f, 0.f, 0.f, 0.f);
        }
    };
    auto stsA = [&](__half* buf) {
        #pragma unroll
        for (int l = 0; l < 4; l++) {
            int f = tid + l * 256;
            int row = f >> 3, c4 = f & 7;
            float4 v = pa[l];
            __half hx = __float2half_rn(v.x), hy = __float2half_rn(v.y);
            __half hz = __float2half_rn(v.z), hw = __float2half_rn(v.w);
            __half lx = __float2half_rn(v.x - __half2float(hx));
            __half ly = __float2half_rn(v.y - __half2float(hy));
            __half lz = __float2half_rn(v.z - __half2float(hz));
            __half lw = __float2half_rn(v.w - __half2float(hw));
            __half2 h0 = __halves2half2(hx, hy), h1v = __halves2half2(hz, hw);
            __half2 l0 = __halves2half2(lx, ly), l1v = __halves2half2(lz, lw);
            *(uint2*)&buf[row * 40 + c4 * 4] =
                make_uint2(*(uint32_t*)&h0, *(uint32_t*)&h1v);
            *(uint2*)&buf[5120 + row * 40 + c4 * 4] =
                make_uint2(*(uint32_t*)&l0, *(uint32_t*)&l1v);
        }
    };
    auto cpB = [&](int kt, __half* buf) {
        #pragma unroll
        for (int l = 0; l < 4; l++) {
            int idx = tid + l * 256;       // 0..1023 chunks of 8 halves
            int sel = idx >> 9;
            int j = idx & 511;
            int r = j >> 2, c8 = j & 3;
            const __half* g = (sel ? g_w1l : g_w1h) + (size_t)r * F_IN + kt + c8 * 8;
            __half* s = buf + 10240 + sel * 5120 + r * 40 + c8 * 8;
            uint32_t sa = smem_u32(s);
            asm volatile("cp.async.cg.shared.global [%0], [%1], 16;\n" :: "r"(sa), "l"(g));
        }
        asm volatile("cp.async.commit_group;\n");
    };

    ldgA(0);
    cpB(0, smh);
    stsA(smh);
    asm volatile("cp.async.wait_group 0;\n");
    __syncthreads();

    for (int s = 0; s < 16; s++) {
        __half* cur = smh + (s & 1) * G1_STAGE_H;
        __half* nxt = smh + ((s + 1) & 1) * G1_STAGE_H;
        if (s + 1 < 16) { cpB((s + 1) * 32, nxt); ldgA((s + 1) * 32); }

        const __half* Ah = cur;
        const __half* Al = cur + 5120;
        const __half* Bh = cur + 10240;
        const __half* Bl = cur + 15360;

        #pragma unroll
        for (int ks = 0; ks < 2; ks++) {
            int kb = ks * 16;
            uint32_t ah[2][4], al[2][4];
            #pragma unroll
            for (int mt = 0; mt < 2; mt++) {
                int r0 = wm + mt * 16 + gid;
                ah[mt][0] = *(const uint32_t*)&Ah[r0 * 40 + kb + tq * 2];
                ah[mt][1] = *(const uint32_t*)&Ah[(r0 + 8) * 40 + kb + tq * 2];
                ah[mt][2] = *(const uint32_t*)&Ah[r0 * 40 + kb + tq * 2 + 8];
                ah[mt][3] = *(const uint32_t*)&Ah[(r0 + 8) * 40 + kb + tq * 2 + 8];
                al[mt][0] = *(const uint32_t*)&Al[r0 * 40 + kb + tq * 2];
                al[mt][1] = *(const uint32_t*)&Al[(r0 + 8) * 40 + kb + tq * 2];
                al[mt][2] = *(const uint32_t*)&Al[r0 * 40 + kb + tq * 2 + 8];
                al[mt][3] = *(const uint32_t*)&Al[(r0 + 8) * 40 + kb + tq * 2 + 8];
            }
            uint32_t bh[8][2], bl[8][2];
            #pragma unroll
            for (int nt = 0; nt < 8; nt++) {
                int n = wn + nt * 8 + gid;
                bh[nt][0] = *(const uint32_t*)&Bh[n * 40 + kb + tq * 2];
                bh[nt][1] = *(const uint32_t*)&Bh[n * 40 + kb + tq * 2 + 8];
                bl[nt][0] = *(const uint32_t*)&Bl[n * 40 + kb + tq * 2];
                bl[nt][1] = *(const uint32_t*)&Bl[n * 40 + kb + tq * 2 + 8];
            }
            #pragma unroll
            for (int mt = 0; mt < 2; mt++)
                #pragma unroll
                for (int nt = 0; nt < 8; nt++) {
                    HMMA(acc[mt][nt], ah[mt], bh[nt]);
                    HMMA(acc[mt][nt], al[mt], bh[nt]);
                    HMMA(acc[mt][nt], ah[mt], bl[nt]);
                }
        }
        if (s + 1 < 16) { stsA(nxt); asm volatile("cp.async.wait_group 0;\n"); }
        __syncthreads();
    }

    #pragma unroll
    for (int mt = 0; mt < 2; mt++) {
        int row = rowBase + wm + mt * 16 + gid;
        #pragma unroll
        for (int nt = 0; nt < 8; nt++) {
            int col = wn + nt * 8 + tq * 2;
            if (row < NN)
                *(__half2*)&g_h1lin_h[(size_t)row * H1 + col] =
                    __floats2half2_rn(acc[mt][nt][0], acc[mt][nt][1]);
            if (row + 8 < NN)
                *(__half2*)&g_h1lin_h[(size_t)(row + 8) * H1 + col] =
                    __floats2half2_rn(acc[mt][nt][2], acc[mt][nt][3]);
        }
    }
}

// ---------------- GEMM2 fp16x2 HMMA: h2lin[100000,64] = h1 @ W2 ----------------
// A is exact fp16 (g_h1_h) -> only 2 terms (A*Bh + A*Bl).
// stage halves: A@0(5120) Bh@5120(2560) Bl@7680 -> 10240
#define G2_STAGE_H 10240
#define G2_SMEM (2 * G2_STAGE_H * 2)

__global__ void __launch_bounds__(256, 1)
k_gemm2_mma() {
    extern __shared__ __half smh[];
    const int tid = threadIdx.x, lane = tid & 31, wid = tid >> 5;
    const int gid = lane >> 2, tq = lane & 3;
    const int rowBase = blockIdx.x * 128;
    const int wm = wid * 16;

    float acc[8][4];
    #pragma unroll
    for (int nt = 0; nt < 8; nt++)
        #pragma unroll
        for (int i = 0; i < 4; i++) acc[nt][i] = 0.f;

    auto cpStage = [&](int kt, __half* buf) {
        // A: 128 rows x 32 halves = 512 chunks of 8
        #pragma unroll
        for (int l = 0; l < 2; l++) {
            int idx = tid + l * 256;
            int r = idx >> 2, c8 = idx & 3;
            int gr = rowBase + r;
            if (gr >= NN) gr = NN - 1;
            const __half* g = g_h1_h + (size_t)gr * H1 + kt + c8 * 8;
            uint32_t sa = smem_u32(buf + r * 40 + c8 * 8);
            asm volatile("cp.async.cg.shared.global [%0], [%1], 16;\n" :: "r"(sa), "l"(g));
        }
        // B: 2 x 64 rows x 32 halves = 512 chunks
        #pragma unroll
        for (int l = 0; l < 2; l++) {
            int idx = tid + l * 256;
            int sel = idx >> 8;
            int j = idx & 255;
            int r = j >> 2, c8 = j & 3;
            const __half* g = (sel ? g_w2l : g_w2h) + (size_t)r * H1 + kt + c8 * 8;
            uint32_t sa = smem_u32(buf + 5120 + sel * 2560 + r * 40 + c8 * 8);
            asm volatile("cp.async.cg.shared.global [%0], [%1], 16;\n" :: "r"(sa), "l"(g));
        }
        asm volatile("cp.async.commit_group;\n");
    };

    cpStage(0, smh);
    asm volatile("cp.async.wait_group 0;\n");
    __syncthreads();

    for (int s = 0; s < 4; s++) {
        __half* cur = smh + (s & 1) * G2_STAGE_H;
        __half* nxt = smh + ((s + 1) & 1) * G2_STAGE_H;
        if (s + 1 < 4) cpStage((s + 1) * 32, nxt);

        const __half* Ah = cur;
        const __half* Bh = cur + 5120;
        const __half* Bl = cur + 7680;

        #pragma unroll
        for (int ks = 0; ks < 2; ks++) {
            int kb = ks * 16;
            int r0 = wm + gid;
            uint32_t a[4];
            a[0] = *(const uint32_t*)&Ah[r0 * 40 + kb + tq * 2];
            a[1] = *(const uint32_t*)&Ah[(r0 + 8) * 40 + kb + tq * 2];
            a[2] = *(const uint32_t*)&Ah[r0 * 40 + kb + tq * 2 + 8];
            a[3] = *(const uint32_t*)&Ah[(r0 + 8) * 40 + kb + tq * 2 + 8];
            #pragma unroll
            for (int nt = 0; nt < 8; nt++) {
                int n = nt * 8 + gid;
                uint32_t bh[2], bl[2];
                bh[0] = *(const uint32_t*)&Bh[n * 40 + kb + tq * 2];
                bh[1] = *(const uint32_t*)&Bh[n * 40 + kb + tq * 2 + 8];
                bl[0] = *(const uint32_t*)&Bl[n * 40 + kb + tq * 2];
                bl[1] = *(const uint32_t*)&Bl[n * 40 + kb + tq * 2 + 8];
                HMMA(acc[nt], a, bh);
                HMMA(acc[nt], a, bl);
            }
        }
        if (s + 1 < 4) asm volatile("cp.async.wait_group 0;\n");
        __syncthreads();
    }

    int row = rowBase + wm + gid;
    #pragma unroll
    for (int nt = 0; nt < 8; nt++) {
        int col = nt * 8 + tq * 2;
        if (row < NN)
            *(__half2*)&g_h2lin_h[(size_t)row * H2 + col] =
                __floats2half2_rn(acc[nt][0], acc[nt][1]);
        if (row + 8 < NN)
            *(__half2*)&g_h2lin_h[(size_t)(row + 8) * H2 + col] =
                __floats2half2_rn(acc[nt][2], acc[nt][3]);
    }
}

// ---------------- gather aggregation (fp16 in, fp32 accum, fp16 out) ----------------
__global__ void k_agg128(const float* __restrict__ bias) {
    int gw = (blockIdx.x * blockDim.x + threadIdx.x) >> 5;
    int lane = threadIdx.x & 31;
    if (gw >= NN) return;
    float dd = g_dinv[gw];
    float w0 = dd * dd;
    uint2 raw = *(const uint2*)&g_h1lin_h[(size_t)gw * H1 + lane * 4];
    float2 f0 = __half22float2(*(__half2*)&raw.x);
    float2 f1 = __half22float2(*(__half2*)&raw.y);
    float4 acc = make_float4(f0.x * w0, f0.y * w0, f1.x * w0, f1.y * w0);
    int s0 = g_rowptr[gw], s1 = g_rowptr[gw + 1];
    for (int base = s0; base < s1; base += 32) {
        int rem = s1 - base;
        int s = 0; float nm = 0.f;
        if (lane < rem) { s = g_csr[base + lane]; nm = dd * g_dinv[s]; }
        int cnt = rem < 32 ? rem : 32;
        for (int j = 0; j < cnt; j++) {
            int ss = __shfl_sync(0xffffffffu, s, j);
            float nn = __shfl_sync(0xffffffffu, nm, j);
            uint2 r2 = *(const uint2*)&g_h1lin_h[(size_t)ss * H1 + lane * 4];
            float2 a0 = __half22float2(*(__half2*)&r2.x);
            float2 a1 = __half22float2(*(__half2*)&r2.y);
            acc.x += nn * a0.x; acc.y += nn * a0.y;
            acc.z += nn * a1.x; acc.w += nn * a1.y;
        }
    }
    float4 bb = ((const float4*)bias)[lane];
    __half2 o0 = __floats2half2_rn(fmaxf(acc.x + bb.x, 0.f), fmaxf(acc.y + bb.y, 0.f));
    __half2 o1 = __floats2half2_rn(fmaxf(acc.z + bb.z, 0.f), fmaxf(acc.w + bb.w, 0.f));
    *(uint2*)&g_h1_h[(size_t)gw * H1 + lane * 4] =
        make_uint2(*(uint32_t*)&o0, *(uint32_t*)&o1);
}

__global__ void k_agg64(const float* __restrict__ bias) {
    int gw = (blockIdx.x * blockDim.x + threadIdx.x) >> 5;
    int lane = threadIdx.x & 31;
    if (gw >= NN) return;
    float dd = g_dinv[gw];
    float w0 = dd * dd;
    float2 f0 = __half22float2(*(const __half2*)&g_h2lin_h[(size_t)gw * H2 + lane * 2]);
    float2 acc = make_float2(f0.x * w0, f0.y * w0);
    int s0 = g_rowptr[gw], s1 = g_rowptr[gw + 1];
    for (int base = s0; base < s1; base += 32) {
        int rem = s1 - base;
        int s = 0; float nm = 0.f;
        if (lane < rem) { s = g_csr[base + lane]; nm = dd * g_dinv[s]; }
        int cnt = rem < 32 ? rem : 32;
        for (int j = 0; j < cnt; j++) {
            int ss = __shfl_sync(0xffffffffu, s, j);
            float nn = __shfl_sync(0xffffffffu, nm, j);
            float2 hv = __half22float2(*(const __half2*)&g_h2lin_h[(size_t)ss * H2 + lane * 2]);
            acc.x += nn * hv.x; acc.y += nn * hv.y;
        }
    }
    float2 bb = ((const float2*)bias)[lane];
    *(__half2*)&g_h2_h[(size_t)gw * H2 + lane * 2] =
        __floats2half2_rn(fmaxf(acc.x + bb.x, 0.f), fmaxf(acc.y + bb.y, 0.f));
}

// ---------------- edge scorer fp16 HMMA ----------------
// halves: Th@0(9216) Tl@9216 Wh@18432(4608) Wl@23040 -> 27648 halves = 55296 B
// floats after: w2s@55296 (128), b1s@55808 (64) -> total 56064 B
#define SC_SMEM 56064

__global__ void __launch_bounds__(256, 1)
k_score_mma(const int* __restrict__ la, const int* __restrict__ lb,
            const float* __restrict__ fcW1, const float* __restrict__ fcb1,
            const float* __restrict__ fcW2, const float* __restrict__ fcb2,
            float* __restrict__ out) {
    extern __shared__ __half smh[];
    __half* Th = smh;
    __half* Tl = smh + 9216;
    __half* Wh = smh + 18432;
    __half* Wl = smh + 23040;
    float* w2s = (float*)((char*)smh + 55296);
    float* b1s = (float*)((char*)smh + 55808);
    const int tid = threadIdx.x, lane = tid & 31, wid = tid >> 5;
    const int gid = lane >> 2, tq = lane & 3;
    const int e0 = blockIdx.x * 128;

    #pragma unroll
    for (int l = 0; l < 16; l++) {
        int idx = tid + l * 256;            // 4096 = 64k x 64n
        int k = idx >> 6, n = idx & 63;
        float w = fcW1[idx];
        __half h = __float2half_rn(w);
        Wh[n * 72 + k] = h;
        Wl[n * 72 + k] = __float2half_rn(w - __half2float(h));
    }
    if (tid < 128) w2s[tid] = fcW2[tid];
    if (tid < 64)  b1s[tid] = fcb1[tid];

    #pragma unroll
    for (int l = 0; l < 4; l++) {
        int idx = tid + l * 256;            // 1024 = 128 edges x 8 chunks
        int e = idx >> 3, c8 = idx & 7;
        int eg = e0 + e;
        if (eg >= NL) eg = NL - 1;
        int a = la[eg], b = lb[eg];
        uint4 va = *(const uint4*)&g_h2_h[(size_t)a * H2 + c8 * 8];
        uint4 vb = *(const uint4*)&g_h2_h[(size_t)b * H2 + c8 * 8];
        uint32_t th[4], tl[4];
        const uint32_t* pa = (const uint32_t*)&va;
        const uint32_t* pb = (const uint32_t*)&vb;
        #pragma unroll
        for (int q = 0; q < 4; q++) {
            float2 fa = __half22float2(*(__half2*)&pa[q]);
            float2 fb = __half22float2(*(__half2*)&pb[q]);
            float px = fa.x * fb.x, py = fa.y * fb.y;
            __half hx = __float2half_rn(px), hy = __float2half_rn(py);
            __half lx = __float2half_rn(px - __half2float(hx));
            __half ly = __float2half_rn(py - __half2float(hy));
            __half2 hh = __halves2half2(hx, hy), ll = __halves2half2(lx, ly);
            th[q] = *(uint32_t*)&hh;
            tl[q] = *(uint32_t*)&ll;
        }
        *(uint4*)&Th[e * 72 + c8 * 8] = make_uint4(th[0], th[1], th[2], th[3]);
        *(uint4*)&Tl[e * 72 + c8 * 8] = make_uint4(tl[0], tl[1], tl[2], tl[3]);
    }
    __syncthreads();

    float acc[8][4];
    #pragma unroll
    for (int nt = 0; nt < 8; nt++)
        #pragma unroll
        for (int i = 0; i < 4; i++) acc[nt][i] = 0.f;

    const int rA = wid * 16 + gid;
    #pragma unroll
    for (int ks = 0; ks < 4; ks++) {
        int kb = ks * 16;
        uint32_t ah[4], al[4];
        ah[0] = *(const uint32_t*)&Th[rA * 72 + kb + tq * 2];
        ah[1] = *(const uint32_t*)&Th[(rA + 8) * 72 + kb + tq * 2];
        ah[2] = *(const uint32_t*)&Th[rA * 72 + kb + tq * 2 + 8];
        ah[3] = *(const uint32_t*)&Th[(rA + 8) * 72 + kb + tq * 2 + 8];
        al[0] = *(const uint32_t*)&Tl[rA * 72 + kb + tq * 2];
        al[1] = *(const uint32_t*)&Tl[(rA + 8) * 72 + kb + tq * 2];
        al[2] = *(const uint32_t*)&Tl[rA * 72 + kb + tq * 2 + 8];
        al[3] = *(const uint32_t*)&Tl[(rA + 8) * 72 + kb + tq * 2 + 8];
        #pragma unroll
        for (int nt = 0; nt < 8; nt++) {
            int n = nt * 8 + gid;
            uint32_t bh[2], bl[2];
            bh[0] = *(const uint32_t*)&Wh[n * 72 + kb + tq * 2];
            bh[1] = *(const uint32_t*)&Wh[n * 72 + kb + tq * 2 + 8];
            bl[0] = *(const uint32_t*)&Wl[n * 72 + kb + tq * 2];
            bl[1] = *(const uint32_t*)&Wl[n * 72 + kb + tq * 2 + 8];
            HMMA(acc[nt], ah, bh);
            HMMA(acc[nt], al, bh);
            HMMA(acc[nt], ah, bl);
        }
    }

    // second tiny layer in registers
    float p00 = 0.f, p01 = 0.f, p10 = 0.f, p11 = 0.f;
    #pragma unroll
    for (int nt = 0; nt < 8; nt++) {
        int col = nt * 8 + tq * 2;
        float4 w2a = *(float4*)&w2s[col * 2];
        float b0v = b1s[col], b1v = b1s[col + 1];
        float u0 = fmaxf(acc[nt][0] + b0v, 0.f);
        float u1 = fmaxf(acc[nt][1] + b1v, 0.f);
        float u2 = fmaxf(acc[nt][2] + b0v, 0.f);
        float u3 = fmaxf(acc[nt][3] + b1v, 0.f);
        p00 += u0 * w2a.x + u1 * w2a.z;
        p01 += u0 * w2a.y + u1 * w2a.w;
        p10 += u2 * w2a.x + u3 * w2a.z;
        p11 += u2 * w2a.y + u3 * w2a.w;
    }
    #pragma unroll
    for (int off = 1; off <= 2; off <<= 1) {
        p00 += __shfl_xor_sync(0xffffffffu, p00, off);
        p01 += __shfl_xor_sync(0xffffffffu, p01, off);
        p10 += __shfl_xor_sync(0xffffffffu, p10, off);
        p11 += __shfl_xor_sync(0xffffffffu, p11, off);
    }
    if (tq == 0) {
        float c0 = fcb2[0], c1 = fcb2[1];
        int e = e0 + wid * 16 + gid;
        if (e < NL)     *(float2*)&out[(size_t)e * 2]       = make_float2(p00 + c0, p01 + c1);
        if (e + 8 < NL) *(float2*)&out[(size_t)(e + 8) * 2] = make_float2(p10 + c0, p11 + c1);
    }
}

// ---------------- launch ----------------
extern "C" void kernel_launch(void* const* d_in, const int* in_sizes, int n_in,
                              void* d_out, int out_size) {
    const float* x    = (const float*)d_in[0];
    const float* W1   = (const float*)d_in[1];
    const float* b1   = (const float*)d_in[2];
    const float* W2   = (const float*)d_in[3];
    const float* b2   = (const float*)d_in[4];
    const float* fcW1 = (const float*)d_in[5];
    const float* fcb1 = (const float*)d_in[6];
    const float* fcW2 = (const float*)d_in[7];
    const float* fcb2 = (const float*)d_in[8];
    const int* eidx = (const int*)d_in[9];
    const int* elab = (const int*)d_in[10];
    const int* src = eidx;
    const int* dst = eidx + NE;
    const int* la = elab;
    const int* lb = elab + NL;
    float* out = (float*)d_out;

    static int attr_done = 0;
    static cudaStream_t s2;
    static cudaEvent_t evA, evB;
    if (!attr_done) {
        cudaFuncSetAttribute(k_gemm1_mma, cudaFuncAttributeMaxDynamicSharedMemorySize, G1_SMEM);
        cudaFuncSetAttribute(k_gemm2_mma, cudaFuncAttributeMaxDynamicSharedMemorySize, G2_SMEM);
        cudaFuncSetAttribute(k_score_mma, cudaFuncAttributeMaxDynamicSharedMemorySize, SC_SMEM);
        cudaStreamCreateWithFlags(&s2, cudaStreamNonBlocking);
        cudaEventCreateWithFlags(&evA, cudaEventDisableTiming);
        cudaEventCreateWithFlags(&evB, cudaEventDisableTiming);
        attr_done = 1;
    }

    // fork: CSR chain on s2, GEMM chain on default
    cudaEventRecord(evA, 0);
    cudaStreamWaitEvent(s2, evA, 0);

    k_zero_count<<<(NN + 255) / 256, 256, 0, s2>>>();
    k_hist<<<(NE + 255) / 256, 256, 0, s2>>>(dst);
    k_dinv<<<(NN + 255) / 256, 256, 0, s2>>>();
    k_bsum<<<NBLK, 1024, 0, s2>>>();
    k_bscan<<<1, 128, 0, s2>>>();
    k_scat<<<NBLK, 1024, 0, s2>>>();
    k_fill<<<(NE + 255) / 256, 256, 0, s2>>>(src, dst);
    cudaEventRecord(evB, s2);

    k_wsplit<<<(H1 * F_IN + 255) / 256, 256>>>(W1);
    k_wsplit2<<<(H2 * H1 + 255) / 256, 256>>>(W2);
    k_gemm1_mma<<<(NN + 127) / 128, 256, G1_SMEM>>>(x);

    // join
    cudaStreamWaitEvent(0, evB, 0);

    k_agg128<<<(NN * 32 + 255) / 256, 256>>>(b1);
    k_gemm2_mma<<<(NN + 127) / 128, 256, G2_SMEM>>>();
    k_agg64<<<(NN * 32 + 255) / 256, 256>>>(b2);
    k_score_mma<<<(NL + 127) / 128, 256, SC_SMEM>>>(la, lb, fcW1, fcb1, fcW2, fcb2, out);
}

// round 7
// speedup vs baseline: 2.1233x; 1.0820x over previous
#include <cuda_runtime.h>
#include <cuda_fp16.h>
#include <math.h>
#include <stdint.h>

#define NN 100000
#define NE 3200000
#define NL 1000000
#define F_IN 512
#define H1 128
#define H2 64
#define NBLK ((NN + 1023) / 1024)

// ---------------- scratch (static device globals; no allocs) ----------------
__device__ __half g_h1lin_s[(size_t)NN * H1];   // fp16 dinv-scaled pre-agg layer1
__device__ __half g_h1_h  [(size_t)NN * H1];    // fp16 post-relu layer1
__device__ __half g_h2lin_s[(size_t)NN * H2];   // fp16 dinv-scaled pre-agg layer2
__device__ __half g_h2_h  [(size_t)NN * H2];    // fp16 post-relu layer2
__device__ float  g_dinv [NN];
__device__ int    g_count[NN];
__device__ int    g_rowptr[NN + 1];
__device__ int    g_cursor[NN];
__device__ int    g_csr  [NE];
__device__ int    g_bsum [NBLK];
__device__ int    g_bpre [NBLK];
__device__ __half g_w1h[(size_t)H1 * F_IN];     // W1^T hi [128][512]
__device__ __half g_w1l[(size_t)H1 * F_IN];     // W1^T lo
__device__ __half g_w2h[(size_t)H2 * H1];       // W2^T hi [64][128]
__device__ __half g_w2l[(size_t)H2 * H1];       // W2^T lo
__device__ __half g_fw1h[(size_t)64 * 64];      // fcW1^T hi [64n][64k]
__device__ __half g_fw1l[(size_t)64 * 64];      // fcW1^T lo

// ---------------- helpers ----------------
__device__ __forceinline__ uint32_t smem_u32(const void* p) {
    uint32_t a;
    asm("{ .reg .u64 t; cvta.to.shared.u64 t, %1; cvt.u32.u64 %0, t; }" : "=r"(a) : "l"(p));
    return a;
}
#define HMMA(c, a, b) \
    asm volatile("mma.sync.aligned.m16n8k16.row.col.f32.f16.f16.f32 " \
                 "{%0,%1,%2,%3}, {%4,%5,%6,%7}, {%8,%9}, {%0,%1,%2,%3};" \
                 : "+f"((c)[0]), "+f"((c)[1]), "+f"((c)[2]), "+f"((c)[3]) \
                 : "r"((a)[0]), "r"((a)[1]), "r"((a)[2]), "r"((a)[3]), \
                   "r"((b)[0]), "r"((b)[1]))

__device__ __forceinline__ void acc8_add(float* acc, uint4 v) {
    const uint32_t* p = (const uint32_t*)&v;
    #pragma unroll
    for (int q = 0; q < 4; q++) {
        float2 f = __half22float2(*(__half2*)&p[q]);
        acc[q * 2] += f.x;
        acc[q * 2 + 1] += f.y;
    }
}

// ---------------- CSR build ----------------
__global__ void k_zero_count() {
    int i = blockIdx.x * blockDim.x + threadIdx.x;
    if (i < NN) g_count[i] = 0;
}
__global__ void k_hist(const int* __restrict__ dst) {
    int i = blockIdx.x * blockDim.x + threadIdx.x;
    if (i < NE) atomicAdd(&g_count[dst[i]], 1);
}
__global__ void k_dinv() {
    int i = blockIdx.x * blockDim.x + threadIdx.x;
    if (i < NN) g_dinv[i] = rsqrtf((float)(g_count[i] + 1));
}
__global__ void k_bsum() {
    __shared__ int ws[32];
    int t = threadIdx.x, lane = t & 31, wid = t >> 5;
    int i = blockIdx.x * 1024 + t;
    int v = (i < NN) ? g_count[i] : 0;
    #pragma unroll
    for (int o = 16; o; o >>= 1) v += __shfl_down_sync(0xffffffffu, v, o);
    if (lane == 0) ws[wid] = v;
    __syncthreads();
    if (wid == 0) {
        int x = ws[lane];
        #pragma unroll
        for (int o = 16; o; o >>= 1) x += __shfl_down_sync(0xffffffffu, x, o);
        if (lane == 0) g_bsum[blockIdx.x] = x;
    }
}
__global__ void k_bscan() {
    __shared__ int ws[4];
    int t = threadIdx.x, lane = t & 31, wid = t >> 5;
    int v = (t < NBLK) ? g_bsum[t] : 0;
    int x = v;
    #pragma unroll
    for (int o = 1; o < 32; o <<= 1) {
        int y = __shfl_up_sync(0xffffffffu, x, o);
        if (lane >= o) x += y;
    }
    if (lane == 31) ws[wid] = x;
    __syncthreads();
    int add = 0;
    for (int w = 0; w < wid; w++) add += ws[w];
    int incl = x + add;
    if (t < NBLK) g_bpre[t] = incl - v;
    if (t == 127) g_rowptr[NN] = incl;
}
__global__ void k_scat() {
    __shared__ int ws[32];
    int t = threadIdx.x, lane = t & 31, wid = t >> 5;
    int i = blockIdx.x * 1024 + t;
    int v = (i < NN) ? g_count[i] : 0;
    int x = v;
    #pragma unroll
    for (int o = 1; o < 32; o <<= 1) {
        int y = __shfl_up_sync(0xffffffffu, x, o);
        if (lane >= o) x += y;
    }
    if (lane == 31) ws[wid] = x;
    __syncthreads();
    if (wid == 0) {
        int w = ws[lane];
        #pragma unroll
        for (int o = 1; o < 32; o <<= 1) {
            int y = __shfl_up_sync(0xffffffffu, w, o);
            if (lane >= o) w += y;
        }
        ws[lane] = w;
    }
    __syncthreads();
    int excl = g_bpre[blockIdx.x] + (wid ? ws[wid - 1] : 0) + x - v;
    if (i < NN) { g_rowptr[i] = excl; g_cursor[i] = excl; }
}
__global__ void k_fill(const int* __restrict__ src, const int* __restrict__ dst) {
    int i = blockIdx.x * blockDim.x + threadIdx.x;
    if (i < NE) {
        int p = atomicAdd(&g_cursor[dst[i]], 1);
        g_csr[p] = src[i];
    }
}

// ---------------- weight transposes + fp16 hi/lo splits ----------------
__global__ void k_wsplit(const float* __restrict__ W1) {
    int i = blockIdx.x * blockDim.x + threadIdx.x;
    if (i < H1 * F_IN) {
        int n = i & (H1 - 1);
        int k = i >> 7;
        float w = W1[(size_t)k * H1 + n];
        __half h = __float2half_rn(w);
        g_w1h[(size_t)n * F_IN + k] = h;
        g_w1l[(size_t)n * F_IN + k] = __float2half_rn(w - __half2float(h));
    }
}
__global__ void k_wsplit2(const float* __restrict__ W2) {
    int i = blockIdx.x * blockDim.x + threadIdx.x;
    if (i < H2 * H1) {
        int n = i & (H2 - 1);
        int k = i >> 6;
        float w = W2[(size_t)k * H2 + n];
        __half h = __float2half_rn(w);
        g_w2h[(size_t)n * H1 + k] = h;
        g_w2l[(size_t)n * H1 + k] = __float2half_rn(w - __half2float(h));
    }
}
__global__ void k_wsplitFC(const float* __restrict__ fcW1) {
    int i = blockIdx.x * blockDim.x + threadIdx.x;
    if (i < 64 * 64) {
        int n = i & 63;
        int k = i >> 6;
        float w = fcW1[(size_t)k * 64 + n];
        __half h = __float2half_rn(w);
        g_fw1h[(size_t)n * 64 + k] = h;
        g_fw1l[(size_t)n * 64 + k] = __float2half_rn(w - __half2float(h));
    }
}

// ---------------- GEMM1 fp16x3 HMMA: h1lin_s = dinv * (x @ W1) ----------------
#define G1_STAGE_H 20480
#define G1_SMEM (2 * G1_STAGE_H * 2)

__global__ void __launch_bounds__(256, 1)
k_gemm1_mma(const float* __restrict__ A) {
    extern __shared__ __half smh[];
    const int tid = threadIdx.x, lane = tid & 31, wid = tid >> 5;
    const int gid = lane >> 2, tq = lane & 3;
    const int rowBase = blockIdx.x * 128;
    const int wm = (wid >> 1) * 32, wn = (wid & 1) * 64;

    float acc[2][8][4];
    #pragma unroll
    for (int mt = 0; mt < 2; mt++)
        #pragma unroll
        for (int nt = 0; nt < 8; nt++)
            #pragma unroll
            for (int i = 0; i < 4; i++) acc[mt][nt][i] = 0.f;

    float4 pa[4];
    auto ldgA = [&](int kt) {
        #pragma unroll
        for (int l = 0; l < 4; l++) {
            int f = tid + l * 256;
            int row = f >> 3, c4 = f & 7;
            int gr = rowBase + row;
            pa[l] = (gr < NN) ? *(const float4*)&A[(size_t)gr * F_IN + kt + c4 * 4]
                              : make_float4(0.f, 0.f, 0.f, 0.f);
        }
    };
    auto stsA = [&](__half* buf) {
        #pragma unroll
        for (int l = 0; l < 4; l++) {
            int f = tid + l * 256;
            int row = f >> 3, c4 = f & 7;
            float4 v = pa[l];
            __half hx = __float2half_rn(v.x), hy = __float2half_rn(v.y);
            __half hz = __float2half_rn(v.z), hw = __float2half_rn(v.w);
            __half lx = __float2half_rn(v.x - __half2float(hx));
            __half ly = __float2half_rn(v.y - __half2float(hy));
            __half lz = __float2half_rn(v.z - __half2float(hz));
            __half lw = __float2half_rn(v.w - __half2float(hw));
            __half2 h0 = __halves2half2(hx, hy), h1v = __halves2half2(hz, hw);
            __half2 l0 = __halves2half2(lx, ly), l1v = __halves2half2(lz, lw);
            *(uint2*)&buf[row * 40 + c4 * 4] =
                make_uint2(*(uint32_t*)&h0, *(uint32_t*)&h1v);
            *(uint2*)&buf[5120 + row * 40 + c4 * 4] =
                make_uint2(*(uint32_t*)&l0, *(uint32_t*)&l1v);
        }
    };
    auto cpB = [&](int kt, __half* buf) {
        #pragma unroll
        for (int l = 0; l < 4; l++) {
            int idx = tid + l * 256;
            int sel = idx >> 9;
            int j = idx & 511;
            int r = j >> 2, c8 = j & 3;
            const __half* g = (sel ? g_w1l : g_w1h) + (size_t)r * F_IN + kt + c8 * 8;
            __half* s = buf + 10240 + sel * 5120 + r * 40 + c8 * 8;
            uint32_t sa = smem_u32(s);
            asm volatile("cp.async.cg.shared.global [%0], [%1], 16;\n" :: "r"(sa), "l"(g));
        }
        asm volatile("cp.async.commit_group;\n");
    };

    ldgA(0);
    cpB(0, smh);
    stsA(smh);
    asm volatile("cp.async.wait_group 0;\n");
    __syncthreads();

    for (int s = 0; s < 16; s++) {
        __half* cur = smh + (s & 1) * G1_STAGE_H;
        __half* nxt = smh + ((s + 1) & 1) * G1_STAGE_H;
        if (s + 1 < 16) { cpB((s + 1) * 32, nxt); ldgA((s + 1) * 32); }

        const __half* Ah = cur;
        const __half* Al = cur + 5120;
        const __half* Bh = cur + 10240;
        const __half* Bl = cur + 15360;

        #pragma unroll
        for (int ks = 0; ks < 2; ks++) {
            int kb = ks * 16;
            uint32_t ah[2][4], al[2][4];
            #pragma unroll
            for (int mt = 0; mt < 2; mt++) {
                int r0 = wm + mt * 16 + gid;
                ah[mt][0] = *(const uint32_t*)&Ah[r0 * 40 + kb + tq * 2];
                ah[mt][1] = *(const uint32_t*)&Ah[(r0 + 8) * 40 + kb + tq * 2];
                ah[mt][2] = *(const uint32_t*)&Ah[r0 * 40 + kb + tq * 2 + 8];
                ah[mt][3] = *(const uint32_t*)&Ah[(r0 + 8) * 40 + kb + tq * 2 + 8];
                al[mt][0] = *(const uint32_t*)&Al[r0 * 40 + kb + tq * 2];
                al[mt][1] = *(const uint32_t*)&Al[(r0 + 8) * 40 + kb + tq * 2];
                al[mt][2] = *(const uint32_t*)&Al[r0 * 40 + kb + tq * 2 + 8];
                al[mt][3] = *(const uint32_t*)&Al[(r0 + 8) * 40 + kb + tq * 2 + 8];
            }
            uint32_t bh[8][2], bl[8][2];
            #pragma unroll
            for (int nt = 0; nt < 8; nt++) {
                int n = wn + nt * 8 + gid;
                bh[nt][0] = *(const uint32_t*)&Bh[n * 40 + kb + tq * 2];
                bh[nt][1] = *(const uint32_t*)&Bh[n * 40 + kb + tq * 2 + 8];
                bl[nt][0] = *(const uint32_t*)&Bl[n * 40 + kb + tq * 2];
                bl[nt][1] = *(const uint32_t*)&Bl[n * 40 + kb + tq * 2 + 8];
            }
            #pragma unroll
            for (int mt = 0; mt < 2; mt++)
                #pragma unroll
                for (int nt = 0; nt < 8; nt++) {
                    HMMA(acc[mt][nt], ah[mt], bh[nt]);
                    HMMA(acc[mt][nt], al[mt], bh[nt]);
                    HMMA(acc[mt][nt], ah[mt], bl[nt]);
                }
        }
        if (s + 1 < 16) { stsA(nxt); asm volatile("cp.async.wait_group 0;\n"); }
        __syncthreads();
    }

    #pragma unroll
    for (int mt = 0; mt < 2; mt++) {
        int row = rowBase + wm + mt * 16 + gid;
        float dv0 = (row < NN) ? g_dinv[row] : 0.f;
        float dv1 = (row + 8 < NN) ? g_dinv[row + 8] : 0.f;
        #pragma unroll
        for (int nt = 0; nt < 8; nt++) {
            int col = wn + nt * 8 + tq * 2;
            if (row < NN)
                *(__half2*)&g_h1lin_s[(size_t)row * H1 + col] =
                    __floats2half2_rn(acc[mt][nt][0] * dv0, acc[mt][nt][1] * dv0);
            if (row + 8 < NN)
                *(__half2*)&g_h1lin_s[(size_t)(row + 8) * H1 + col] =
                    __floats2half2_rn(acc[mt][nt][2] * dv1, acc[mt][nt][3] * dv1);
        }
    }
}

// ---------------- GEMM2 fp16x2 HMMA: h2lin_s = dinv * (h1 @ W2) ----------------
#define G2_STAGE_H 10240
#define G2_SMEM (2 * G2_STAGE_H * 2)

__global__ void __launch_bounds__(256, 1)
k_gemm2_mma() {
    extern __shared__ __half smh[];
    const int tid = threadIdx.x, lane = tid & 31, wid = tid >> 5;
    const int gid = lane >> 2, tq = lane & 3;
    const int rowBase = blockIdx.x * 128;
    const int wm = wid * 16;

    float acc[8][4];
    #pragma unroll
    for (int nt = 0; nt < 8; nt++)
        #pragma unroll
        for (int i = 0; i < 4; i++) acc[nt][i] = 0.f;

    auto cpStage = [&](int kt, __half* buf) {
        #pragma unroll
        for (int l = 0; l < 2; l++) {
            int idx = tid + l * 256;
            int r = idx >> 2, c8 = idx & 3;
            int gr = rowBase + r;
            if (gr >= NN) gr = NN - 1;
            const __half* g = g_h1_h + (size_t)gr * H1 + kt + c8 * 8;
            uint32_t sa = smem_u32(buf + r * 40 + c8 * 8);
            asm volatile("cp.async.cg.shared.global [%0], [%1], 16;\n" :: "r"(sa), "l"(g));
        }
        #pragma unroll
        for (int l = 0; l < 2; l++) {
            int idx = tid + l * 256;
            int sel = idx >> 8;
            int j = idx & 255;
            int r = j >> 2, c8 = j & 3;
            const __half* g = (sel ? g_w2l : g_w2h) + (size_t)r * H1 + kt + c8 * 8;
            uint32_t sa = smem_u32(buf + 5120 + sel * 2560 + r * 40 + c8 * 8);
            asm volatile("cp.async.cg.shared.global [%0], [%1], 16;\n" :: "r"(sa), "l"(g));
        }
        asm volatile("cp.async.commit_group;\n");
    };

    cpStage(0, smh);
    asm volatile("cp.async.wait_group 0;\n");
    __syncthreads();

    for (int s = 0; s < 4; s++) {
        __half* cur = smh + (s & 1) * G2_STAGE_H;
        __half* nxt = smh + ((s + 1) & 1) * G2_STAGE_H;
        if (s + 1 < 4) cpStage((s + 1) * 32, nxt);

        const __half* Ah = cur;
        const __half* Bh = cur + 5120;
        const __half* Bl = cur + 7680;

        #pragma unroll
        for (int ks = 0; ks < 2; ks++) {
            int kb = ks * 16;
            int r0 = wm + gid;
            uint32_t a[4];
            a[0] = *(const uint32_t*)&Ah[r0 * 40 + kb + tq * 2];
            a[1] = *(const uint32_t*)&Ah[(r0 + 8) * 40 + kb + tq * 2];
            a[2] = *(const uint32_t*)&Ah[r0 * 40 + kb + tq * 2 + 8];
            a[3] = *(const uint32_t*)&Ah[(r0 + 8) * 40 + kb + tq * 2 + 8];
            #pragma unroll
            for (int nt = 0; nt < 8; nt++) {
                int n = nt * 8 + gid;
                uint32_t bh[2], bl[2];
                bh[0] = *(const uint32_t*)&Bh[n * 40 + kb + tq * 2];
                bh[1] = *(const uint32_t*)&Bh[n * 40 + kb + tq * 2 + 8];
                bl[0] = *(const uint32_t*)&Bl[n * 40 + kb + tq * 2];
                bl[1] = *(const uint32_t*)&Bl[n * 40 + kb + tq * 2 + 8];
                HMMA(acc[nt], a, bh);
                HMMA(acc[nt], a, bl);
            }
        }
        if (s + 1 < 4) asm volatile("cp.async.wait_group 0;\n");
        __syncthreads();
    }

    int row = rowBase + wm + gid;
    float dv0 = (row < NN) ? g_dinv[row] : 0.f;
    float dv1 = (row + 8 < NN) ? g_dinv[row + 8] : 0.f;
    #pragma unroll
    for (int nt = 0; nt < 8; nt++) {
        int col = nt * 8 + tq * 2;
        if (row < NN)
            *(__half2*)&g_h2lin_s[(size_t)row * H2 + col] =
                __floats2half2_rn(acc[nt][0] * dv0, acc[nt][1] * dv0);
        if (row + 8 < NN)
            *(__half2*)&g_h2lin_s[(size_t)(row + 8) * H2 + col] =
                __floats2half2_rn(acc[nt][2] * dv1, acc[nt][3] * dv1);
    }
}

// ---------------- aggregation: pure row-sum of pre-scaled fp16 rows ----------------
// agg128: 1 warp/node, half-warp per row (uint4/lane), 2 rows per iteration
__global__ void k_agg128(const float* __restrict__ bias) {
    int gw = (blockIdx.x * blockDim.x + threadIdx.x) >> 5;
    int lane = threadIdx.x & 31;
    if (gw >= NN) return;
    int half = lane >> 4, fl = lane & 15;
    const uint4* H = (const uint4*)g_h1lin_s;
    float acc[8];
    #pragma unroll
    for (int i = 0; i < 8; i++) acc[i] = 0.f;
    if (half == 0) acc8_add(acc, H[(size_t)gw * 16 + fl]);   // self row (scaled)
    int s0 = g_rowptr[gw], s1 = g_rowptr[gw + 1];
    for (int base = s0; base < s1; base += 32) {
        int rem = s1 - base;
        int cnt = rem < 32 ? rem : 32;
        int s = (lane < rem) ? g_csr[base + lane] : 0;
        for (int jj = 0; jj < cnt; jj += 2) {
            int j = jj + half;
            int ss = __shfl_sync(0xffffffffu, s, j < cnt ? j : 0);
            if (j < cnt) acc8_add(acc, H[(size_t)ss * 16 + fl]);
        }
    }
    #pragma unroll
    for (int i = 0; i < 8; i++) acc[i] += __shfl_xor_sync(0xffffffffu, acc[i], 16);
    if (half == 0) {
        float dd = g_dinv[gw];
        float4 b0 = *(const float4*)&bias[fl * 8];
        float4 b1 = *(const float4*)&bias[fl * 8 + 4];
        __half2 o[4];
        o[0] = __floats2half2_rn(fmaxf(acc[0] * dd + b0.x, 0.f), fmaxf(acc[1] * dd + b0.y, 0.f));
        o[1] = __floats2half2_rn(fmaxf(acc[2] * dd + b0.z, 0.f), fmaxf(acc[3] * dd + b0.w, 0.f));
        o[2] = __floats2half2_rn(fmaxf(acc[4] * dd + b1.x, 0.f), fmaxf(acc[5] * dd + b1.y, 0.f));
        o[3] = __floats2half2_rn(fmaxf(acc[6] * dd + b1.z, 0.f), fmaxf(acc[7] * dd + b1.w, 0.f));
        ((uint4*)g_h1_h)[(size_t)gw * 16 + fl] =
            make_uint4(*(uint32_t*)&o[0], *(uint32_t*)&o[1], *(uint32_t*)&o[2], *(uint32_t*)&o[3]);
    }
}

// agg64: 1 warp/node, 8 lanes per row (uint4/lane), 4 rows per iteration
__global__ void k_agg64(const float* __restrict__ bias) {
    int gw = (blockIdx.x * blockDim.x + threadIdx.x) >> 5;
    int lane = threadIdx.x & 31;
    if (gw >= NN) return;
    int q4 = lane >> 3, fl = lane & 7;
    const uint4* H = (const uint4*)g_h2lin_s;
    float acc[8];
    #pragma unroll
    for (int i = 0; i < 8; i++) acc[i] = 0.f;
    if (q4 == 0) acc8_add(acc, H[(size_t)gw * 8 + fl]);      // self row (scaled)
    int s0 = g_rowptr[gw], s1 = g_rowptr[gw + 1];
    for (int base = s0; base < s1; base += 32) {
        int rem = s1 - base;
        int cnt = rem < 32 ? rem : 32;
        int s = (lane < rem) ? g_csr[base + lane] : 0;
        for (int jj = 0; jj < cnt; jj += 4) {
            int j = jj + q4;
            int ss = __shfl_sync(0xffffffffu, s, j < cnt ? j : 0);
            if (j < cnt) acc8_add(acc, H[(size_t)ss * 8 + fl]);
        }
    }
    #pragma unroll
    for (int i = 0; i < 8; i++) {
        acc[i] += __shfl_xor_sync(0xffffffffu, acc[i], 8);
        acc[i] += __shfl_xor_sync(0xffffffffu, acc[i], 16);
    }
    if (q4 == 0 && (lane >> 3) == 0) {
        float dd = g_dinv[gw];
        float4 b0 = *(const float4*)&bias[fl * 8];
        float4 b1 = *(const float4*)&bias[fl * 8 + 4];
        __half2 o[4];
        o[0] = __floats2half2_rn(fmaxf(acc[0] * dd + b0.x, 0.f), fmaxf(acc[1] * dd + b0.y, 0.f));
        o[1] = __floats2half2_rn(fmaxf(acc[2] * dd + b0.z, 0.f), fmaxf(acc[3] * dd + b0.w, 0.f));
        o[2] = __floats2half2_rn(fmaxf(acc[4] * dd + b1.x, 0.f), fmaxf(acc[5] * dd + b1.y, 0.f));
        o[3] = __floats2half2_rn(fmaxf(acc[6] * dd + b1.z, 0.f), fmaxf(acc[7] * dd + b1.w, 0.f));
        ((uint4*)g_h2_h)[(size_t)gw * 8 + fl] =
            make_uint4(*(uint32_t*)&o[0], *(uint32_t*)&o[1], *(uint32_t*)&o[2], *(uint32_t*)&o[3]);
    }
}

// ---------------- edge scorer fp16 HMMA ----------------
// halves: Th@0(9216) Tl@9216 Wh@18432(4608) Wl@23040 -> 27648 halves = 55296 B
// floats after: w2s@55296 (128), b1s@55808 (64) -> total 56064 B
#define SC_SMEM 56064

__global__ void __launch_bounds__(256, 1)
k_score_mma(const int* __restrict__ la, const int* __restrict__ lb,
            const float* __restrict__ fcb1,
            const float* __restrict__ fcW2, const float* __restrict__ fcb2,
            float* __restrict__ out) {
    extern __shared__ __half smh[];
    __half* Th = smh;
    __half* Tl = smh + 9216;
    __half* Wh = smh + 18432;
    __half* Wl = smh + 23040;
    float* w2s = (float*)((char*)smh + 55296);
    float* b1s = (float*)((char*)smh + 55808);
    const int tid = threadIdx.x, lane = tid & 31, wid = tid >> 5;
    const int gid = lane >> 2, tq = lane & 3;
    const int e0 = blockIdx.x * 128;

    // W1 hi/lo via cp.async (pre-split, pre-transposed): 64 rows x 64 halves each
    #pragma unroll
    for (int l = 0; l < 4; l++) {
        int idx = tid + l * 256;             // 1024 = 2 x (64 rows x 8 chunks)
        int sel = idx >> 9;
        int j = idx & 511;
        int n = j >> 3, c8 = j & 7;
        const __half* g = (sel ? g_fw1l : g_fw1h) + (size_t)n * 64 + c8 * 8;
        __half* s = (sel ? Wl : Wh) + n * 72 + c8 * 8;
        uint32_t sa = smem_u32(s);
        asm volatile("cp.async.cg.shared.global [%0], [%1], 16;\n" :: "r"(sa), "l"(g));
    }
    asm volatile("cp.async.commit_group;\n");
    if (tid < 128) w2s[tid] = fcW2[tid];
    if (tid < 64)  b1s[tid] = fcb1[tid];

    #pragma unroll
    for (int l = 0; l < 4; l++) {
        int idx = tid + l * 256;             // 1024 = 128 edges x 8 chunks
        int e = idx >> 3, c8 = idx & 7;
        int eg = e0 + e;
        if (eg >= NL) eg = NL - 1;
        int a = la[eg], b = lb[eg];
        uint4 va = *(const uint4*)&g_h2_h[(size_t)a * H2 + c8 * 8];
        uint4 vb = *(const uint4*)&g_h2_h[(size_t)b * H2 + c8 * 8];
        uint32_t th[4], tl[4];
        const uint32_t* pa = (const uint32_t*)&va;
        const uint32_t* pb = (const uint32_t*)&vb;
        #pragma unroll
        for (int q = 0; q < 4; q++) {
            float2 fa = __half22float2(*(__half2*)&pa[q]);
            float2 fb = __half22float2(*(__half2*)&pb[q]);
            float px = fa.x * fb.x, py = fa.y * fb.y;
            __half hx = __float2half_rn(px), hy = __float2half_rn(py);
            __half lx = __float2half_rn(px - __half2float(hx));
            __half ly = __float2half_rn(py - __half2float(hy));
            __half2 hh = __halves2half2(hx, hy), ll = __halves2half2(lx, ly);
            th[q] = *(uint32_t*)&hh;
            tl[q] = *(uint32_t*)&ll;
        }
        *(uint4*)&Th[e * 72 + c8 * 8] = make_uint4(th[0], th[1], th[2], th[3]);
        *(uint4*)&Tl[e * 72 + c8 * 8] = make_uint4(tl[0], tl[1], tl[2], tl[3]);
    }
    asm volatile("cp.async.wait_group 0;\n");
    __syncthreads();

    float acc[8][4];
    #pragma unroll
    for (int nt = 0; nt < 8; nt++)
        #pragma unroll
        for (int i = 0; i < 4; i++) acc[nt][i] = 0.f;

    const int rA = wid * 16 + gid;
    #pragma unroll
    for (int ks = 0; ks < 4; ks++) {
        int kb = ks * 16;
        uint32_t ah[4], al[4];
        ah[0] = *(const uint32_t*)&Th[rA * 72 + kb + tq * 2];
        ah[1] = *(const uint32_t*)&Th[(rA + 8) * 72 + kb + tq * 2];
        ah[2] = *(const uint32_t*)&Th[rA * 72 + kb + tq * 2 + 8];
        ah[3] = *(const uint32_t*)&Th[(rA + 8) * 72 + kb + tq * 2 + 8];
        al[0] = *(const uint32_t*)&Tl[rA * 72 + kb + tq * 2];
        al[1] = *(const uint32_t*)&Tl[(rA + 8) * 72 + kb + tq * 2];
        al[2] = *(const uint32_t*)&Tl[rA * 72 + kb + tq * 2 + 8];
        al[3] = *(const uint32_t*)&Tl[(rA + 8) * 72 + kb + tq * 2 + 8];
        #pragma unroll
        for (int nt = 0; nt < 8; nt++) {
            int n = nt * 8 + gid;
            uint32_t bh[2], bl[2];
            bh[0] = *(const uint32_t*)&Wh[n * 72 + kb + tq * 2];
            bh[1] = *(const uint32_t*)&Wh[n * 72 + kb + tq * 2 + 8];
            bl[0] = *(const uint32_t*)&Wl[n * 72 + kb + tq * 2];
            bl[1] = *(const uint32_t*)&Wl[n * 72 + kb + tq * 2 + 8];
            HMMA(acc[nt], ah, bh);
            HMMA(acc[nt], al, bh);
            HMMA(acc[nt], ah, bl);
        }
    }

    // second tiny layer in registers
    float p00 = 0.f, p01 = 0.f, p10 = 0.f, p11 = 0.f;
    #pragma unroll
    for (int nt = 0; nt < 8; nt++) {
        int col = nt * 8 + tq * 2;
        float4 w2a = *(float4*)&w2s[col * 2];
        float b0v = b1s[col], b1v = b1s[col + 1];
        float u0 = fmaxf(acc[nt][0] + b0v, 0.f);
        float u1 = fmaxf(acc[nt][1] + b1v, 0.f);
        float u2 = fmaxf(acc[nt][2] + b0v, 0.f);
        float u3 = fmaxf(acc[nt][3] + b1v, 0.f);
        p00 += u0 * w2a.x + u1 * w2a.z;
        p01 += u0 * w2a.y + u1 * w2a.w;
        p10 += u2 * w2a.x + u3 * w2a.z;
        p11 += u2 * w2a.y + u3 * w2a.w;
    }
    #pragma unroll
    for (int off = 1; off <= 2; off <<= 1) {
        p00 += __shfl_xor_sync(0xffffffffu, p00, off);
        p01 += __shfl_xor_sync(0xffffffffu, p01, off);
        p10 += __shfl_xor_sync(0xffffffffu, p10, off);
        p11 += __shfl_xor_sync(0xffffffffu, p11, off);
    }
    if (tq == 0) {
        float c0 = fcb2[0], c1 = fcb2[1];
        int e = e0 + wid * 16 + gid;
        if (e < NL)     *(float2*)&out[(size_t)e * 2]       = make_float2(p00 + c0, p01 + c1);
        if (e + 8 < NL) *(float2*)&out[(size_t)(e + 8) * 2] = make_float2(p10 + c0, p11 + c1);
    }
}

// ---------------- launch ----------------
extern "C" void kernel_launch(void* const* d_in, const int* in_sizes, int n_in,
                              void* d_out, int out_size) {
    const float* x    = (const float*)d_in[0];
    const float* W1   = (const float*)d_in[1];
    const float* b1   = (const float*)d_in[2];
    const float* W2   = (const float*)d_in[3];
    const float* b2   = (const float*)d_in[4];
    const float* fcW1 = (const float*)d_in[5];
    const float* fcb1 = (const float*)d_in[6];
    const float* fcW2 = (const float*)d_in[7];
    const float* fcb2 = (const float*)d_in[8];
    const int* eidx = (const int*)d_in[9];
    const int* elab = (const int*)d_in[10];
    const int* src = eidx;
    const int* dst = eidx + NE;
    const int* la = elab;
    const int* lb = elab + NL;
    float* out = (float*)d_out;

    static int attr_done = 0;
    static cudaStream_t s2;
    static cudaEvent_t evA, evB;
    if (!attr_done) {
        cudaFuncSetAttribute(k_gemm1_mma, cudaFuncAttributeMaxDynamicSharedMemorySize, G1_SMEM);
        cudaFuncSetAttribute(k_gemm2_mma, cudaFuncAttributeMaxDynamicSharedMemorySize, G2_SMEM);
        cudaFuncSetAttribute(k_score_mma, cudaFuncAttributeMaxDynamicSharedMemorySize, SC_SMEM);
        cudaStreamCreateWithFlags(&s2, cudaStreamNonBlocking);
        cudaEventCreateWithFlags(&evA, cudaEventDisableTiming);
        cudaEventCreateWithFlags(&evB, cudaEventDisableTiming);
        attr_done = 1;
    }

    // serial prefix: degrees (gemm epilogues need g_dinv)
    k_zero_count<<<(NN + 255) / 256, 256>>>();
    k_hist<<<(NE + 255) / 256, 256>>>(dst);
    k_dinv<<<(NN + 255) / 256, 256>>>();

    // fork: rest of CSR build on s2, weight prep + gemm1 on default
    cudaEventRecord(evA, 0);
    cudaStreamWaitEvent(s2, evA, 0);

    k_bsum<<<NBLK, 1024, 0, s2>>>();
    k_bscan<<<1, 128, 0, s2>>>();
    k_scat<<<NBLK, 1024, 0, s2>>>();
    k_fill<<<(NE + 255) / 256, 256, 0, s2>>>(src, dst);
    cudaEventRecord(evB, s2);

    k_wsplit<<<(H1 * F_IN + 255) / 256, 256>>>(W1);
    k_wsplit2<<<(H2 * H1 + 255) / 256, 256>>>(W2);
    k_wsplitFC<<<(64 * 64 + 255) / 256, 256>>>(fcW1);
    k_gemm1_mma<<<(NN + 127) / 128, 256, G1_SMEM>>>(x);

    // join
    cudaStreamWaitEvent(0, evB, 0);

    k_agg128<<<(NN * 32 + 255) / 256, 256>>>(b1);
    k_gemm2_mma<<<(NN + 127) / 128, 256, G2_SMEM>>>();
    k_agg64<<<(NN * 32 + 255) / 256, 256>>>(b2);
    k_score_mma<<<(NL + 127) / 128, 256, SC_SMEM>>>(la, lb, fcb1, fcW2, fcb2, out);
}